// round 13
// baseline (speedup 1.0000x reference)
#include <cuda_runtime.h>
#include <cuda_bf16.h>
#include <math.h>

// ---------------- scratch (static device globals; no allocation) ----------------
static __device__ __align__(16) float g_pfeat[2818048];
static __device__ __align__(16) unsigned g_h2p[20480 * 128];   // LN2 out, K=256 (frag-packed)
static __device__ __align__(16) unsigned g_mlpp[20480 * 256];  // gelu out, K=512 (frag-packed)
static __device__ __align__(16) unsigned g_w1[128 * 512];   // fc1 W frag-packed
static __device__ __align__(16) unsigned g_w2[256 * 256];   // fc2 W frag-packed

__device__ __forceinline__ unsigned pack_bf2(float lo, float hi) {
    __nv_bfloat162 h = __floats2bfloat162_rn(lo, hi);
    return *(unsigned*)&h;
}

// word (row r, k-pair kp) -> index into fragment-packed A array (unsigned units)
__device__ __forceinline__ size_t apack_widx(int r, int kp, int K16) {
    return (((size_t)(r >> 4) * K16 + (kp >> 3)) * 32 + ((r & 7) * 4 + (kp & 3))) * 4
           + (size_t)(((kp >> 2) & 1) * 2 + ((r >> 3) & 1));
}

// ---------------- pre-pack weights + bias-init split pfeat + x0 copy (merged) ----------------
__global__ void convert_w(const float* __restrict__ fc1W, const float* __restrict__ fc2W,
                          const float* __restrict__ ep2b, const float* __restrict__ ep3b,
                          const float* __restrict__ ep4b,
                          const float* __restrict__ x, float* __restrict__ out) {
    int i = blockIdx.x * blockDim.x + threadIdx.x;    // 0..491519
    if (i < 32768) {
        bool is2 = i >= 16384;
        int j = is2 ? i - 16384 : i;
        const float* Wsrc = is2 ? fc2W : fc1W;
        int N = is2 ? 256 : 512;
        int GG = N / 16;
        int lane = j & 31;
        int gg = (j >> 5) % GG;
        int ks = (j >> 5) / GG;
        int gid = lane >> 2, tig = lane & 3;
        int col = gg * 16 + gid;
        int k0 = ks * 16 + 2 * tig;
        uint4 u;
        u.x = pack_bf2(Wsrc[(size_t)(k0 + 0) * N + col],     Wsrc[(size_t)(k0 + 1) * N + col]);
        u.y = pack_bf2(Wsrc[(size_t)(k0 + 8) * N + col],     Wsrc[(size_t)(k0 + 9) * N + col]);
        u.z = pack_bf2(Wsrc[(size_t)(k0 + 0) * N + col + 8], Wsrc[(size_t)(k0 + 1) * N + col + 8]);
        u.w = pack_bf2(Wsrc[(size_t)(k0 + 8) * N + col + 8], Wsrc[(size_t)(k0 + 9) * N + col + 8]);
        ((uint4*)(is2 ? (void*)g_w2 : (void*)g_w1))[j] = u;
    } else if (i < 229376) {
        // bias-init pfeat regions for split levels L2/L3/L4: [2621440, 2818048)
        int idx = i - 32768;               // 0..196607
        const float* bp = (idx < 131072) ? ep2b : (idx < 163840 ? ep3b : ep4b);
        g_pfeat[2621440 + idx] = bp[idx & 31];
    } else {
        // copy x0 token slice: 262144 float4s
        int j = i - 229376;
        int b = j >> 16;
        int r = j & 65535;
        size_t off = (size_t)b * (6 * 65536) + r;
        ((float4*)out)[off] = ((const float4*)x)[off];
    }
}

// ---------------- merged feature projection, channel-split for large C ----------------
struct ProjParams {
    const float* feat[5];
    const float* W[5];
    const float* bias[5];
};

__global__ __launch_bounds__(256) void proj_all(ProjParams P) {
    const int starts[6] = {0, 64, 96, 224, 480, 1504};
    const int levs[5]   = {3, 4, 2, 1, 0};
    const int shifts[5] = {2, 1, 1, 0, 0};
    const int Cs[5]   = {64, 128, 256, 512, 256};
    const int HWs[5]  = {16384, 4096, 1024, 256, 256};
    const int offs[5] = {0, 2097152, 2621440, 2752512, 2785280};

    __shared__ float featS[32][64];
    __shared__ float WS[32][32];

    int blk = blockIdx.x;
    int gi = 0;
#pragma unroll
    for (int i = 0; i < 4; i++) if (blk >= starts[gi + 1]) gi++;
    int l = levs[gi];
    int shift = shifts[gi];
    int split = 1 << shift;
    int rel = blk - starts[gi];
    int tile = rel >> shift;
    int s = rel & (split - 1);

    int C = Cs[l], HW = HWs[l];
    int Cper = C >> shift;
    int c_base = s * Cper;
    int pixbase = tile * 64;
    int b = pixbase / HW;
    int idx0 = pixbase - b * HW;

    const float* feat = P.feat[l];
    const float* Wp = P.W[l];
    const float* bp = P.bias[l];

    int t = threadIdx.x;
    int px = t & 63, grp = t >> 6;

    float acc[8];
#pragma unroll
    for (int j = 0; j < 8; j++) acc[j] = (split == 1) ? bp[grp * 8 + j] : 0.0f;

    size_t fbase = ((size_t)b * C) * HW + idx0;

    for (int c0 = c_base; c0 < c_base + Cper; c0 += 32) {
        __syncthreads();
#pragma unroll
        for (int k = 0; k < 8; k++) {
            int j = t + k * 256;
            int cc = j >> 6, pp = j & 63;
            featS[cc][pp] = feat[fbase + (size_t)(c0 + cc) * HW + pp];
        }
#pragma unroll
        for (int k = 0; k < 4; k++) {
            int j = t + k * 256;
            WS[j >> 5][j & 31] = Wp[(size_t)(c0 + (j >> 5)) * 32 + (j & 31)];
        }
        __syncthreads();
#pragma unroll
        for (int cc = 0; cc < 32; cc++) {
            float fv = featS[cc][px];
#pragma unroll
            for (int j = 0; j < 8; j++)
                acc[j] = fmaf(fv, WS[cc][grp * 8 + j], acc[j]);
        }
    }
    float* o = g_pfeat + offs[l] + (size_t)(pixbase + px) * 32 + grp * 8;
    if (split == 1) {
        *(float4*)o = make_float4(acc[0], acc[1], acc[2], acc[3]);
        *(float4*)(o + 4) = make_float4(acc[4], acc[5], acc[6], acc[7]);
    } else {
#pragma unroll
        for (int j = 0; j < 8; j++) atomicAdd(o + j, acc[j]);
    }
}

// ---------------- fused token kernel: 8 tokens per block, 256 threads ----------------
__global__ __launch_bounds__(256) void token_fused(
    const float* __restrict__ x, const float* __restrict__ ref,
    const float* __restrict__ n1g, const float* __restrict__ n1b,
    const float* __restrict__ awW, const float* __restrict__ awb,
    const float* __restrict__ soW, const float* __restrict__ sob,
    const float* __restrict__ n2g, const float* __restrict__ n2b,
    float* __restrict__ out) {
    __shared__ __align__(16) float hT_sh[256][12];
    __shared__ float logit_sh[8][96];
    __shared__ float logit2_sh[8][96];
    __shared__ float aw_sh[8][32];
    __shared__ __align__(16) int   tap_sh[8][32][4];
    __shared__ __align__(16) float wgt_sh[8][32][4];
    __shared__ float o_sh[8][256];

    int t = threadIdx.x, lane = t & 31, w = t >> 5;
    int m0 = blockIdx.x * 8;
    int b = m0 / 5120;
    int lp = m0 - b * 5120;
    int l = lp >> 10;
    int p0 = lp & 1023;
    size_t base_q = ((size_t)(b * 6 + l + 1) * 1024 + p0) * 256;
    size_t base_0 = ((size_t)(b * 6) * 1024 + p0) * 256;

    const int lvlW_[5] = {128, 64, 32, 16, 16};
    const int lvlOff_[5] = {0, 2097152, 2621440, 2752512, 2785280};
    const int W = lvlW_[l];
    const float* lvlbase = g_pfeat + lvlOff_[l] + (size_t)b * W * W * 32;

    // ---- P1: LN1 ----
    {
        size_t xq_off = base_q + (size_t)w * 256;
        size_t x0_off = base_0 + (size_t)w * 256;
        float sv[8];
        float s = 0.0f;
#pragma unroll
        for (int i = 0; i < 8; i++) {
            int c = lane + 32 * i;
            sv[i] = x[xq_off + c] + x[x0_off + c];
            s += sv[i];
        }
#pragma unroll
        for (int o = 16; o > 0; o >>= 1) s += __shfl_xor_sync(0xffffffffu, s, o);
        float mean = s * (1.0f / 256.0f);
        float v = 0.0f;
#pragma unroll
        for (int i = 0; i < 8; i++) { float d = sv[i] - mean; v += d * d; }
#pragma unroll
        for (int o = 16; o > 0; o >>= 1) v += __shfl_xor_sync(0xffffffffu, v, o);
        float rstd = rsqrtf(v * (1.0f / 256.0f) + 1e-5f);
#pragma unroll
        for (int i = 0; i < 8; i++) {
            int c = lane + 32 * i;
            hT_sh[c][w] = (sv[i] - mean) * rstd * n1g[c] + n1b[c];
        }
    }
    __syncthreads();

    // ---- P2: head logits, k-split (192 threads) ----
    if (t < 192) {
        int half = t >= 96;
        int j = t - 96 * half;
        int k0 = half * 128;
        const float* wcol;
        int stride;
        float bias = 0.0f;
        if (j < 32) { wcol = awW + j; stride = 32; if (!half) bias = awb[j]; }
        else        { wcol = soW + (j - 32); stride = 64; if (!half) bias = sob[j - 32]; }
        wcol += (size_t)k0 * stride;
        float acc0 = bias, acc1 = bias, acc2 = bias, acc3 = bias;
        float acc4 = bias, acc5 = bias, acc6 = bias, acc7 = bias;
#pragma unroll 8
        for (int k = 0; k < 128; k++) {
            float wv = __ldg(wcol + (size_t)k * stride);
            float4 hA = *(const float4*)&hT_sh[k0 + k][0];
            float4 hB = *(const float4*)&hT_sh[k0 + k][4];
            acc0 = fmaf(hA.x, wv, acc0);
            acc1 = fmaf(hA.y, wv, acc1);
            acc2 = fmaf(hA.z, wv, acc2);
            acc3 = fmaf(hA.w, wv, acc3);
            acc4 = fmaf(hB.x, wv, acc4);
            acc5 = fmaf(hB.y, wv, acc5);
            acc6 = fmaf(hB.z, wv, acc6);
            acc7 = fmaf(hB.w, wv, acc7);
        }
        float (*dst)[96] = half ? logit2_sh : logit_sh;
        dst[0][j] = acc0; dst[1][j] = acc1;
        dst[2][j] = acc2; dst[3][j] = acc3;
        dst[4][j] = acc4; dst[5][j] = acc5;
        dst[6][j] = acc6; dst[7][j] = acc7;
    }
    __syncthreads();

    // ---- P3a: softmax ----
    if (t < 64) {
        int tok = t >> 3, hd = t & 7;
        float v0 = logit_sh[tok][hd * 4 + 0] + logit2_sh[tok][hd * 4 + 0];
        float v1 = logit_sh[tok][hd * 4 + 1] + logit2_sh[tok][hd * 4 + 1];
        float v2 = logit_sh[tok][hd * 4 + 2] + logit2_sh[tok][hd * 4 + 2];
        float v3 = logit_sh[tok][hd * 4 + 3] + logit2_sh[tok][hd * 4 + 3];
        float mx = fmaxf(fmaxf(v0, v1), fmaxf(v2, v3));
        float e0 = expf(v0 - mx), e1 = expf(v1 - mx), e2 = expf(v2 - mx), e3 = expf(v3 - mx);
        float inv = 1.0f / (e0 + e1 + e2 + e3);
        aw_sh[tok][hd * 4 + 0] = e0 * inv;
        aw_sh[tok][hd * 4 + 1] = e1 * inv;
        aw_sh[tok][hd * 4 + 2] = e2 * inv;
        aw_sh[tok][hd * 4 + 3] = e3 * inv;
    }
    __syncthreads();

    // ---- P3b: taps + combined weights ----
    {
        int tok = t >> 5, q = lane;
        float rx = ref[((size_t)b * 1024 + p0 + tok) * 2 + 0];
        float ry = ref[((size_t)b * 1024 + p0 + tok) * 2 + 1];
        float lx = logit_sh[tok][32 + 2 * q + 0] + logit2_sh[tok][32 + 2 * q + 0];
        float ly = logit_sh[tok][32 + 2 * q + 1] + logit2_sh[tok][32 + 2 * q + 1];
        float px_ = tanhf(lx) + rx;
        float py_ = tanhf(ly) + ry;
        float fw = (float)(W - 1);
        float gx = fminf(fmaxf((px_ + 1.0f) * 0.5f * fw, 0.0f), fw);
        float gy = fminf(fmaxf((py_ + 1.0f) * 0.5f * fw, 0.0f), fw);
        float x0f = floorf(gx), y0f = floorf(gy);
        float wx = gx - x0f, wy = gy - y0f;
        int x0i = (int)x0f, y0i = (int)y0f;
        int x1i = min(x0i + 1, W - 1), y1i = min(y0i + 1, W - 1);
        *(int4*)tap_sh[tok][q] = make_int4((y0i * W + x0i) * 32, (y0i * W + x1i) * 32,
                                           (y1i * W + x0i) * 32, (y1i * W + x1i) * 32);
        float a = aw_sh[tok][q];
        *(float4*)wgt_sh[tok][q] = make_float4(a * (1.0f - wx) * (1.0f - wy),
                                               a * wx * (1.0f - wy),
                                               a * (1.0f - wx) * wy,
                                               a * wx * wy);
    }
    __syncthreads();

    // ---- P4: coalesced gather + head accumulate ----
#pragma unroll
    for (int iter = 0; iter < 2; iter++) {
        int slot = t + 256 * iter;
        int tok = slot >> 6;
        int head = (slot >> 3) & 7;
        int cg = (slot & 7) * 4;
        float ax = 0.0f, ay = 0.0f, az = 0.0f, aw4 = 0.0f;
#pragma unroll
        for (int s = 0; s < 4; s++) {
            int q = head * 4 + s;
            int4 tp = *(const int4*)tap_sh[tok][q];
            float4 wt = *(const float4*)wgt_sh[tok][q];
            float4 f0 = *(const float4*)(lvlbase + tp.x + cg);
            float4 f1 = *(const float4*)(lvlbase + tp.y + cg);
            float4 f2 = *(const float4*)(lvlbase + tp.z + cg);
            float4 f3 = *(const float4*)(lvlbase + tp.w + cg);
            ax = fmaf(wt.x, f0.x, fmaf(wt.y, f1.x, fmaf(wt.z, f2.x, fmaf(wt.w, f3.x, ax))));
            ay = fmaf(wt.x, f0.y, fmaf(wt.y, f1.y, fmaf(wt.z, f2.y, fmaf(wt.w, f3.y, ay))));
            az = fmaf(wt.x, f0.z, fmaf(wt.y, f1.z, fmaf(wt.z, f2.z, fmaf(wt.w, f3.z, az))));
            aw4 = fmaf(wt.x, f0.w, fmaf(wt.y, f1.w, fmaf(wt.z, f2.w, fmaf(wt.w, f3.w, aw4))));
        }
        *(float4*)&o_sh[tok][head * 32 + cg] = make_float4(ax, ay, az, aw4);
    }
    __syncthreads();

    // ---- P5: residual + LN2 -> fragment-packed bf16 h2 ----
    {
        size_t xq_off = base_q + (size_t)w * 256;
        int r = m0 + w;
        float o8[8];
        float s = 0.0f;
#pragma unroll
        for (int i = 0; i < 4; i++) {
            int c0 = 2 * lane + 64 * i;
            float2 xv = *(const float2*)(x + xq_off + c0);
            float v0 = xv.x + o_sh[w][c0];
            float v1 = xv.y + o_sh[w][c0 + 1];
            *(float2*)(out + xq_off + c0) = make_float2(v0, v1);
            o8[2 * i] = v0; o8[2 * i + 1] = v1;
            s += v0 + v1;
        }
#pragma unroll
        for (int o = 16; o > 0; o >>= 1) s += __shfl_xor_sync(0xffffffffu, s, o);
        float mean = s * (1.0f / 256.0f);
        float v = 0.0f;
#pragma unroll
        for (int i = 0; i < 8; i++) { float d = o8[i] - mean; v += d * d; }
#pragma unroll
        for (int o = 16; o > 0; o >>= 1) v += __shfl_xor_sync(0xffffffffu, v, o);
        float rstd = rsqrtf(v * (1.0f / 256.0f) + 1e-5f);
#pragma unroll
        for (int i = 0; i < 4; i++) {
            int c0 = 2 * lane + 64 * i;
            float2 g2 = *(const float2*)(n2g + c0);
            float2 b2 = *(const float2*)(n2b + c0);
            float h0 = (o8[2 * i] - mean) * rstd * g2.x + b2.x;
            float h1 = (o8[2 * i + 1] - mean) * rstd * g2.y + b2.y;
            g_h2p[apack_widx(r, lane + 32 * i, 16)] = pack_bf2(h0, h1);
        }
    }
}

// ---------------- bf16 tensor-core GEMM: no smem, no syncs, M-tile 64 ----------------
// Block = 8 warps: wm (4) x 16 rows, wn (2) x 64 cols. Tile 64x128.
template <int K, int NDIM, int EPI>
__global__ __launch_bounds__(256, 3) void mma_gemm(const float* __restrict__ bias,
                                                   float* __restrict__ out) {
    const uint4* A4 = (EPI == 0) ? (const uint4*)g_h2p : (const uint4*)g_mlpp;
    const uint4* B4 = (EPI == 0) ? (const uint4*)g_w1 : (const uint4*)g_w2;
    const int K16 = K / 16;
    const int GG = NDIM / 16;

    int tid = threadIdx.x;
    int m0 = blockIdx.y * 64, n0 = blockIdx.x * 128;
    int lane = tid & 31, wid = tid >> 5;
    int wm = wid & 3, wn = wid >> 2;
    int gid = lane >> 2, tig = lane & 3;

    int mtile = (m0 >> 4) + wm;
    const uint4* Ap = A4 + ((size_t)mtile * K16) * 32 + lane;
    const uint4* Bp = B4 + ((size_t)(n0 >> 4) + wn * 4) * 32 + lane;
    const size_t bstep = (size_t)GG * 32;

    float acc[8][4];
#pragma unroll
    for (int nt = 0; nt < 8; nt++)
#pragma unroll
        for (int r = 0; r < 4; r++) acc[nt][r] = 0.0f;

#pragma unroll 4
    for (int ks = 0; ks < K16; ks++) {
        uint4 a0 = __ldg(Ap + ks * 32);
        uint4 b0 = __ldg(Bp + ks * bstep);
        uint4 b1 = __ldg(Bp + ks * bstep + 32);
        uint4 b2 = __ldg(Bp + ks * bstep + 64);
        uint4 b3 = __ldg(Bp + ks * bstep + 96);
        const uint4 bb[4] = {b0, b1, b2, b3};
#pragma unroll
        for (int p = 0; p < 4; p++) {
            uint4 q = bb[p];
            asm volatile(
                "mma.sync.aligned.m16n8k16.row.col.f32.bf16.bf16.f32 "
                "{%0,%1,%2,%3},{%4,%5,%6,%7},{%8,%9},{%0,%1,%2,%3};"
                : "+f"(acc[2 * p][0]), "+f"(acc[2 * p][1]),
                  "+f"(acc[2 * p][2]), "+f"(acc[2 * p][3])
                : "r"(a0.x), "r"(a0.y), "r"(a0.z), "r"(a0.w), "r"(q.x), "r"(q.y));
            asm volatile(
                "mma.sync.aligned.m16n8k16.row.col.f32.bf16.bf16.f32 "
                "{%0,%1,%2,%3},{%4,%5,%6,%7},{%8,%9},{%0,%1,%2,%3};"
                : "+f"(acc[2 * p + 1][0]), "+f"(acc[2 * p + 1][1]),
                  "+f"(acc[2 * p + 1][2]), "+f"(acc[2 * p + 1][3])
                : "r"(a0.x), "r"(a0.y), "r"(a0.z), "r"(a0.w), "r"(q.z), "r"(q.w));
        }
    }

#pragma unroll
    for (int nt = 0; nt < 8; nt++) {
        int r0 = m0 + wm * 16 + gid;
        int c = n0 + wn * 64 + nt * 8 + 2 * tig;
        float bv0 = __ldg(bias + c), bv1 = __ldg(bias + c + 1);
        if (EPI == 0) {
            float v0 = acc[nt][0] + bv0, v1 = acc[nt][1] + bv1;
            float v2 = acc[nt][2] + bv0, v3 = acc[nt][3] + bv1;
            uint2 u = make_uint2(pack_bf2(v0 * normcdff(v0), v1 * normcdff(v1)),
                                 pack_bf2(v2 * normcdff(v2), v3 * normcdff(v3)));
            *(uint2*)&g_mlpp[apack_widx(r0, c >> 1, 32)] = u;
        } else {
#pragma unroll
            for (int half = 0; half < 2; half++) {
                int row = r0 + half * 8;
                int bb = row / 5120;
                int lpp = row - bb * 5120;
                int ll = lpp >> 10;
                int pp = lpp & 1023;
                float* orow = out + ((size_t)(bb * 6 + ll + 1) * 1024 + pp) * 256 + c;
                float2 cur = *(float2*)orow;
                cur.x += acc[nt][half * 2 + 0] + bv0;
                cur.y += acc[nt][half * 2 + 1] + bv1;
                *(float2*)orow = cur;
            }
        }
    }
}

// ---------------- launch ----------------
extern "C" void kernel_launch(void* const* d_in, const int* in_sizes, int n_in,
                              void* d_out, int out_size) {
    const float* x    = (const float*)d_in[0];
    const float* ref  = (const float*)d_in[1];
    const float* n1g = (const float*)d_in[7];
    const float* n1b = (const float*)d_in[8];
    const float* awW = (const float*)d_in[9];
    const float* awb = (const float*)d_in[10];
    const float* soW = (const float*)d_in[11];
    const float* sob = (const float*)d_in[12];
    const float* n2g  = (const float*)d_in[23];
    const float* n2b  = (const float*)d_in[24];
    const float* fc1W = (const float*)d_in[25];
    const float* fc1b = (const float*)d_in[26];
    const float* fc2W = (const float*)d_in[27];
    const float* fc2b = (const float*)d_in[28];
    float* out = (float*)d_out;

    ProjParams P;
    for (int lvl = 0; lvl < 5; lvl++) {
        P.feat[lvl] = (const float*)d_in[2 + lvl];
        P.W[lvl]    = (const float*)d_in[13 + 2 * lvl];
        P.bias[lvl] = (const float*)d_in[14 + 2 * lvl];
    }

    convert_w<<<1920, 256>>>(fc1W, fc2W, P.bias[2], P.bias[3], P.bias[4], x, out);
    proj_all<<<1504, 256>>>(P);
    token_fused<<<2560, 256>>>(x, ref, n1g, n1b, awW, awb, soW, sob, n2g, n2b, out);
    mma_gemm<256, 512, 0><<<dim3(4, 320), 256>>>(fc1b, out);
    mma_gemm<512, 256, 1><<<dim3(2, 320), 256>>>(fc2b, out);
}

// round 14
// speedup vs baseline: 1.3155x; 1.3155x over previous
#include <cuda_runtime.h>
#include <cuda_bf16.h>
#include <math.h>

// ---------------- scratch (static device globals; no allocation) ----------------
static __device__ __align__(16) float g_pfeat[2818048];
static __device__ __align__(16) unsigned g_h2p[20480 * 128];   // LN2 out, K=256 (frag-packed)
static __device__ __align__(16) unsigned g_mlpp[20480 * 256];  // gelu out, K=512 (frag-packed)
static __device__ __align__(16) unsigned g_w1[128 * 512];   // fc1 W frag-packed
static __device__ __align__(16) unsigned g_w2[256 * 256];   // fc2 W frag-packed

__device__ __forceinline__ unsigned pack_bf2(float lo, float hi) {
    __nv_bfloat162 h = __floats2bfloat162_rn(lo, hi);
    return *(unsigned*)&h;
}

// word (row r, k-pair kp) -> index into fragment-packed A array (unsigned units)
__device__ __forceinline__ size_t apack_widx(int r, int kp, int K16) {
    return (((size_t)(r >> 4) * K16 + (kp >> 3)) * 32 + ((r & 7) * 4 + (kp & 3))) * 4
           + (size_t)(((kp >> 2) & 1) * 2 + ((r >> 3) & 1));
}

__device__ __forceinline__ float gelu_exact(float v) {
    return v * (0.5f * (1.0f + erff(v * 0.70710678118654752f)));
}

// ---------------- pre-pack weights + bias-init split pfeat + x0 copy (merged) ----------------
__global__ void convert_w(const float* __restrict__ fc1W, const float* __restrict__ fc2W,
                          const float* __restrict__ ep2b, const float* __restrict__ ep3b,
                          const float* __restrict__ ep4b,
                          const float* __restrict__ x, float* __restrict__ out) {
    int i = blockIdx.x * blockDim.x + threadIdx.x;    // 0..491519
    if (i < 32768) {
        bool is2 = i >= 16384;
        int j = is2 ? i - 16384 : i;
        const float* Wsrc = is2 ? fc2W : fc1W;
        int N = is2 ? 256 : 512;
        int GG = N / 16;
        int lane = j & 31;
        int gg = (j >> 5) % GG;
        int ks = (j >> 5) / GG;
        int gid = lane >> 2, tig = lane & 3;
        int col = gg * 16 + gid;
        int k0 = ks * 16 + 2 * tig;
        uint4 u;
        u.x = pack_bf2(Wsrc[(size_t)(k0 + 0) * N + col],     Wsrc[(size_t)(k0 + 1) * N + col]);
        u.y = pack_bf2(Wsrc[(size_t)(k0 + 8) * N + col],     Wsrc[(size_t)(k0 + 9) * N + col]);
        u.z = pack_bf2(Wsrc[(size_t)(k0 + 0) * N + col + 8], Wsrc[(size_t)(k0 + 1) * N + col + 8]);
        u.w = pack_bf2(Wsrc[(size_t)(k0 + 8) * N + col + 8], Wsrc[(size_t)(k0 + 9) * N + col + 8]);
        ((uint4*)(is2 ? (void*)g_w2 : (void*)g_w1))[j] = u;
    } else if (i < 229376) {
        // bias-init pfeat regions for split levels L2/L3/L4: [2621440, 2818048)
        int idx = i - 32768;               // 0..196607
        const float* bp = (idx < 131072) ? ep2b : (idx < 163840 ? ep3b : ep4b);
        g_pfeat[2621440 + idx] = bp[idx & 31];
    } else {
        // copy x0 token slice: 262144 float4s
        int j = i - 229376;
        int b = j >> 16;
        int r = j & 65535;
        size_t off = (size_t)b * (6 * 65536) + r;
        ((float4*)out)[off] = ((const float4*)x)[off];
    }
}

// ---------------- merged feature projection, channel-split for large C ----------------
struct ProjParams {
    const float* feat[5];
    const float* W[5];
    const float* bias[5];
};

__global__ __launch_bounds__(256) void proj_all(ProjParams P) {
    const int starts[6] = {0, 64, 96, 224, 480, 1504};
    const int levs[5]   = {3, 4, 2, 1, 0};
    const int shifts[5] = {2, 1, 1, 0, 0};
    const int Cs[5]   = {64, 128, 256, 512, 256};
    const int HWs[5]  = {16384, 4096, 1024, 256, 256};
    const int offs[5] = {0, 2097152, 2621440, 2752512, 2785280};

    __shared__ float featS[32][64];
    __shared__ float WS[32][32];

    int blk = blockIdx.x;
    int gi = 0;
#pragma unroll
    for (int i = 0; i < 4; i++) if (blk >= starts[gi + 1]) gi++;
    int l = levs[gi];
    int shift = shifts[gi];
    int split = 1 << shift;
    int rel = blk - starts[gi];
    int tile = rel >> shift;
    int s = rel & (split - 1);

    int C = Cs[l], HW = HWs[l];
    int Cper = C >> shift;
    int c_base = s * Cper;
    int pixbase = tile * 64;
    int b = pixbase / HW;
    int idx0 = pixbase - b * HW;

    const float* feat = P.feat[l];
    const float* Wp = P.W[l];
    const float* bp = P.bias[l];

    int t = threadIdx.x;
    int px = t & 63, grp = t >> 6;

    float acc[8];
#pragma unroll
    for (int j = 0; j < 8; j++) acc[j] = (split == 1) ? bp[grp * 8 + j] : 0.0f;

    size_t fbase = ((size_t)b * C) * HW + idx0;

    for (int c0 = c_base; c0 < c_base + Cper; c0 += 32) {
        __syncthreads();
#pragma unroll
        for (int k = 0; k < 8; k++) {
            int j = t + k * 256;
            int cc = j >> 6, pp = j & 63;
            featS[cc][pp] = feat[fbase + (size_t)(c0 + cc) * HW + pp];
        }
#pragma unroll
        for (int k = 0; k < 4; k++) {
            int j = t + k * 256;
            WS[j >> 5][j & 31] = Wp[(size_t)(c0 + (j >> 5)) * 32 + (j & 31)];
        }
        __syncthreads();
#pragma unroll
        for (int cc = 0; cc < 32; cc++) {
            float fv = featS[cc][px];
#pragma unroll
            for (int j = 0; j < 8; j++)
                acc[j] = fmaf(fv, WS[cc][grp * 8 + j], acc[j]);
        }
    }
    float* o = g_pfeat + offs[l] + (size_t)(pixbase + px) * 32 + grp * 8;
    if (split == 1) {
        *(float4*)o = make_float4(acc[0], acc[1], acc[2], acc[3]);
        *(float4*)(o + 4) = make_float4(acc[4], acc[5], acc[6], acc[7]);
    } else {
#pragma unroll
        for (int j = 0; j < 8; j++) atomicAdd(o + j, acc[j]);
    }
}

// ---------------- fused token kernel: 8 tokens per block, 256 threads ----------------
__global__ __launch_bounds__(256) void token_fused(
    const float* __restrict__ x, const float* __restrict__ ref,
    const float* __restrict__ n1g, const float* __restrict__ n1b,
    const float* __restrict__ awW, const float* __restrict__ awb,
    const float* __restrict__ soW, const float* __restrict__ sob,
    const float* __restrict__ n2g, const float* __restrict__ n2b,
    float* __restrict__ out) {
    __shared__ __align__(16) float hT_sh[256][12];
    __shared__ float logit_sh[8][96];
    __shared__ float logit2_sh[8][96];
    __shared__ float aw_sh[8][32];
    __shared__ __align__(16) int   tap_sh[8][32][4];
    __shared__ __align__(16) float wgt_sh[8][32][4];
    __shared__ float o_sh[8][256];

    int t = threadIdx.x, lane = t & 31, w = t >> 5;
    int m0 = blockIdx.x * 8;
    int b = m0 / 5120;
    int lp = m0 - b * 5120;
    int l = lp >> 10;
    int p0 = lp & 1023;
    size_t base_q = ((size_t)(b * 6 + l + 1) * 1024 + p0) * 256;
    size_t base_0 = ((size_t)(b * 6) * 1024 + p0) * 256;

    const int lvlW_[5] = {128, 64, 32, 16, 16};
    const int lvlOff_[5] = {0, 2097152, 2621440, 2752512, 2785280};
    const int W = lvlW_[l];
    const float* lvlbase = g_pfeat + lvlOff_[l] + (size_t)b * W * W * 32;

    // ---- P1: LN1 ----
    {
        size_t xq_off = base_q + (size_t)w * 256;
        size_t x0_off = base_0 + (size_t)w * 256;
        float sv[8];
        float s = 0.0f;
#pragma unroll
        for (int i = 0; i < 8; i++) {
            int c = lane + 32 * i;
            sv[i] = x[xq_off + c] + x[x0_off + c];
            s += sv[i];
        }
#pragma unroll
        for (int o = 16; o > 0; o >>= 1) s += __shfl_xor_sync(0xffffffffu, s, o);
        float mean = s * (1.0f / 256.0f);
        float v = 0.0f;
#pragma unroll
        for (int i = 0; i < 8; i++) { float d = sv[i] - mean; v += d * d; }
#pragma unroll
        for (int o = 16; o > 0; o >>= 1) v += __shfl_xor_sync(0xffffffffu, v, o);
        float rstd = rsqrtf(v * (1.0f / 256.0f) + 1e-5f);
#pragma unroll
        for (int i = 0; i < 8; i++) {
            int c = lane + 32 * i;
            hT_sh[c][w] = (sv[i] - mean) * rstd * n1g[c] + n1b[c];
        }
    }
    __syncthreads();

    // ---- P2: head logits, k-split (192 threads) ----
    if (t < 192) {
        int half = t >= 96;
        int j = t - 96 * half;
        int k0 = half * 128;
        const float* wcol;
        int stride;
        float bias = 0.0f;
        if (j < 32) { wcol = awW + j; stride = 32; if (!half) bias = awb[j]; }
        else        { wcol = soW + (j - 32); stride = 64; if (!half) bias = sob[j - 32]; }
        wcol += (size_t)k0 * stride;
        float acc0 = bias, acc1 = bias, acc2 = bias, acc3 = bias;
        float acc4 = bias, acc5 = bias, acc6 = bias, acc7 = bias;
#pragma unroll 8
        for (int k = 0; k < 128; k++) {
            float wv = __ldg(wcol + (size_t)k * stride);
            float4 hA = *(const float4*)&hT_sh[k0 + k][0];
            float4 hB = *(const float4*)&hT_sh[k0 + k][4];
            acc0 = fmaf(hA.x, wv, acc0);
            acc1 = fmaf(hA.y, wv, acc1);
            acc2 = fmaf(hA.z, wv, acc2);
            acc3 = fmaf(hA.w, wv, acc3);
            acc4 = fmaf(hB.x, wv, acc4);
            acc5 = fmaf(hB.y, wv, acc5);
            acc6 = fmaf(hB.z, wv, acc6);
            acc7 = fmaf(hB.w, wv, acc7);
        }
        float (*dst)[96] = half ? logit2_sh : logit_sh;
        dst[0][j] = acc0; dst[1][j] = acc1;
        dst[2][j] = acc2; dst[3][j] = acc3;
        dst[4][j] = acc4; dst[5][j] = acc5;
        dst[6][j] = acc6; dst[7][j] = acc7;
    }
    __syncthreads();

    // ---- P3a: softmax ----
    if (t < 64) {
        int tok = t >> 3, hd = t & 7;
        float v0 = logit_sh[tok][hd * 4 + 0] + logit2_sh[tok][hd * 4 + 0];
        float v1 = logit_sh[tok][hd * 4 + 1] + logit2_sh[tok][hd * 4 + 1];
        float v2 = logit_sh[tok][hd * 4 + 2] + logit2_sh[tok][hd * 4 + 2];
        float v3 = logit_sh[tok][hd * 4 + 3] + logit2_sh[tok][hd * 4 + 3];
        float mx = fmaxf(fmaxf(v0, v1), fmaxf(v2, v3));
        float e0 = expf(v0 - mx), e1 = expf(v1 - mx), e2 = expf(v2 - mx), e3 = expf(v3 - mx);
        float inv = 1.0f / (e0 + e1 + e2 + e3);
        aw_sh[tok][hd * 4 + 0] = e0 * inv;
        aw_sh[tok][hd * 4 + 1] = e1 * inv;
        aw_sh[tok][hd * 4 + 2] = e2 * inv;
        aw_sh[tok][hd * 4 + 3] = e3 * inv;
    }
    __syncthreads();

    // ---- P3b: taps + combined weights ----
    {
        int tok = t >> 5, q = lane;
        float rx = ref[((size_t)b * 1024 + p0 + tok) * 2 + 0];
        float ry = ref[((size_t)b * 1024 + p0 + tok) * 2 + 1];
        float lx = logit_sh[tok][32 + 2 * q + 0] + logit2_sh[tok][32 + 2 * q + 0];
        float ly = logit_sh[tok][32 + 2 * q + 1] + logit2_sh[tok][32 + 2 * q + 1];
        float px_ = tanhf(lx) + rx;
        float py_ = tanhf(ly) + ry;
        float fw = (float)(W - 1);
        float gx = fminf(fmaxf((px_ + 1.0f) * 0.5f * fw, 0.0f), fw);
        float gy = fminf(fmaxf((py_ + 1.0f) * 0.5f * fw, 0.0f), fw);
        float x0f = floorf(gx), y0f = floorf(gy);
        float wx = gx - x0f, wy = gy - y0f;
        int x0i = (int)x0f, y0i = (int)y0f;
        int x1i = min(x0i + 1, W - 1), y1i = min(y0i + 1, W - 1);
        *(int4*)tap_sh[tok][q] = make_int4((y0i * W + x0i) * 32, (y0i * W + x1i) * 32,
                                           (y1i * W + x0i) * 32, (y1i * W + x1i) * 32);
        float a = aw_sh[tok][q];
        *(float4*)wgt_sh[tok][q] = make_float4(a * (1.0f - wx) * (1.0f - wy),
                                               a * wx * (1.0f - wy),
                                               a * (1.0f - wx) * wy,
                                               a * wx * wy);
    }
    __syncthreads();

    // ---- P4: coalesced gather + head accumulate ----
#pragma unroll
    for (int iter = 0; iter < 2; iter++) {
        int slot = t + 256 * iter;
        int tok = slot >> 6;
        int head = (slot >> 3) & 7;
        int cg = (slot & 7) * 4;
        float ax = 0.0f, ay = 0.0f, az = 0.0f, aw4 = 0.0f;
#pragma unroll
        for (int s = 0; s < 4; s++) {
            int q = head * 4 + s;
            int4 tp = *(const int4*)tap_sh[tok][q];
            float4 wt = *(const float4*)wgt_sh[tok][q];
            float4 f0 = *(const float4*)(lvlbase + tp.x + cg);
            float4 f1 = *(const float4*)(lvlbase + tp.y + cg);
            float4 f2 = *(const float4*)(lvlbase + tp.z + cg);
            float4 f3 = *(const float4*)(lvlbase + tp.w + cg);
            ax = fmaf(wt.x, f0.x, fmaf(wt.y, f1.x, fmaf(wt.z, f2.x, fmaf(wt.w, f3.x, ax))));
            ay = fmaf(wt.x, f0.y, fmaf(wt.y, f1.y, fmaf(wt.z, f2.y, fmaf(wt.w, f3.y, ay))));
            az = fmaf(wt.x, f0.z, fmaf(wt.y, f1.z, fmaf(wt.z, f2.z, fmaf(wt.w, f3.z, az))));
            aw4 = fmaf(wt.x, f0.w, fmaf(wt.y, f1.w, fmaf(wt.z, f2.w, fmaf(wt.w, f3.w, aw4))));
        }
        *(float4*)&o_sh[tok][head * 32 + cg] = make_float4(ax, ay, az, aw4);
    }
    __syncthreads();

    // ---- P5: residual + LN2 -> fragment-packed bf16 h2 ----
    {
        size_t xq_off = base_q + (size_t)w * 256;
        int r = m0 + w;
        float o8[8];
        float s = 0.0f;
#pragma unroll
        for (int i = 0; i < 4; i++) {
            int c0 = 2 * lane + 64 * i;
            float2 xv = *(const float2*)(x + xq_off + c0);
            float v0 = xv.x + o_sh[w][c0];
            float v1 = xv.y + o_sh[w][c0 + 1];
            *(float2*)(out + xq_off + c0) = make_float2(v0, v1);
            o8[2 * i] = v0; o8[2 * i + 1] = v1;
            s += v0 + v1;
        }
#pragma unroll
        for (int o = 16; o > 0; o >>= 1) s += __shfl_xor_sync(0xffffffffu, s, o);
        float mean = s * (1.0f / 256.0f);
        float v = 0.0f;
#pragma unroll
        for (int i = 0; i < 8; i++) { float d = o8[i] - mean; v += d * d; }
#pragma unroll
        for (int o = 16; o > 0; o >>= 1) v += __shfl_xor_sync(0xffffffffu, v, o);
        float rstd = rsqrtf(v * (1.0f / 256.0f) + 1e-5f);
#pragma unroll
        for (int i = 0; i < 4; i++) {
            int c0 = 2 * lane + 64 * i;
            float2 g2 = *(const float2*)(n2g + c0);
            float2 b2 = *(const float2*)(n2b + c0);
            float h0 = (o8[2 * i] - mean) * rstd * g2.x + b2.x;
            float h1 = (o8[2 * i + 1] - mean) * rstd * g2.y + b2.y;
            g_h2p[apack_widx(r, lane + 32 * i, 16)] = pack_bf2(h0, h1);
        }
    }
}

// ---------------- bf16 tensor-core GEMM: no smem, no syncs (R11 config, M-tile 128) ----------------
template <int K, int NDIM, int EPI>
__global__ __launch_bounds__(256) void mma_gemm(const float* __restrict__ bias,
                                                float* __restrict__ out) {
    const uint4* A4 = (EPI == 0) ? (const uint4*)g_h2p : (const uint4*)g_mlpp;
    const uint4* B4 = (EPI == 0) ? (const uint4*)g_w1 : (const uint4*)g_w2;
    const int K16 = K / 16;
    const int GG = NDIM / 16;

    int tid = threadIdx.x;
    int m0 = blockIdx.y * 128, n0 = blockIdx.x * 128;
    int lane = tid & 31, wid = tid >> 5;
    int wm = wid & 3, wn = wid >> 2;
    int gid = lane >> 2, tig = lane & 3;

    int mtile = (m0 + wm * 32) >> 4;
    const uint4* Ap = A4 + ((size_t)mtile * K16) * 32 + lane;
    const uint4* Bp = B4 + ((size_t)(n0 >> 4) + wn * 4) * 32 + lane;
    const size_t bstep = (size_t)GG * 32;

    float acc[2][8][4];
#pragma unroll
    for (int mt = 0; mt < 2; mt++)
#pragma unroll
        for (int nt = 0; nt < 8; nt++)
#pragma unroll
            for (int r = 0; r < 4; r++) acc[mt][nt][r] = 0.0f;

#pragma unroll 4
    for (int ks = 0; ks < K16; ks++) {
        uint4 a0 = __ldg(Ap + ks * 32);
        uint4 a1 = __ldg(Ap + (size_t)(K16 + ks) * 32);
        uint4 b0 = __ldg(Bp + ks * bstep);
        uint4 b1 = __ldg(Bp + ks * bstep + 32);
        uint4 b2 = __ldg(Bp + ks * bstep + 64);
        uint4 b3 = __ldg(Bp + ks * bstep + 96);
        const uint4 bb[4] = {b0, b1, b2, b3};
#pragma unroll
        for (int p = 0; p < 4; p++) {
            uint4 q = bb[p];
#pragma unroll
            for (int mt = 0; mt < 2; mt++) {
                uint4 a = mt ? a1 : a0;
                asm volatile(
                    "mma.sync.aligned.m16n8k16.row.col.f32.bf16.bf16.f32 "
                    "{%0,%1,%2,%3},{%4,%5,%6,%7},{%8,%9},{%0,%1,%2,%3};"
                    : "+f"(acc[mt][2 * p][0]), "+f"(acc[mt][2 * p][1]),
                      "+f"(acc[mt][2 * p][2]), "+f"(acc[mt][2 * p][3])
                    : "r"(a.x), "r"(a.y), "r"(a.z), "r"(a.w), "r"(q.x), "r"(q.y));
                asm volatile(
                    "mma.sync.aligned.m16n8k16.row.col.f32.bf16.bf16.f32 "
                    "{%0,%1,%2,%3},{%4,%5,%6,%7},{%8,%9},{%0,%1,%2,%3};"
                    : "+f"(acc[mt][2 * p + 1][0]), "+f"(acc[mt][2 * p + 1][1]),
                      "+f"(acc[mt][2 * p + 1][2]), "+f"(acc[mt][2 * p + 1][3])
                    : "r"(a.x), "r"(a.y), "r"(a.z), "r"(a.w), "r"(q.z), "r"(q.w));
            }
        }
    }

#pragma unroll
    for (int mt = 0; mt < 2; mt++) {
#pragma unroll
        for (int nt = 0; nt < 8; nt++) {
            int r0 = m0 + wm * 32 + mt * 16 + gid;
            int c = n0 + wn * 64 + nt * 8 + 2 * tig;
            float bv0 = __ldg(bias + c), bv1 = __ldg(bias + c + 1);
            if (EPI == 0) {
                float v0 = acc[mt][nt][0] + bv0, v1 = acc[mt][nt][1] + bv1;
                float v2 = acc[mt][nt][2] + bv0, v3 = acc[mt][nt][3] + bv1;
                uint2 u = make_uint2(pack_bf2(gelu_exact(v0), gelu_exact(v1)),
                                     pack_bf2(gelu_exact(v2), gelu_exact(v3)));
                *(uint2*)&g_mlpp[apack_widx(r0, c >> 1, 32)] = u;
            } else {
#pragma unroll
                for (int half = 0; half < 2; half++) {
                    int row = r0 + half * 8;
                    int bb = row / 5120;
                    int lpp = row - bb * 5120;
                    int ll = lpp >> 10;
                    int pp = lpp & 1023;
                    float* orow = out + ((size_t)(bb * 6 + ll + 1) * 1024 + pp) * 256 + c;
                    float2 cur = *(float2*)orow;
                    cur.x += acc[mt][nt][half * 2 + 0] + bv0;
                    cur.y += acc[mt][nt][half * 2 + 1] + bv1;
                    *(float2*)orow = cur;
                }
            }
        }
    }
}

// ---------------- launch ----------------
extern "C" void kernel_launch(void* const* d_in, const int* in_sizes, int n_in,
                              void* d_out, int out_size) {
    const float* x    = (const float*)d_in[0];
    const float* ref  = (const float*)d_in[1];
    const float* n1g = (const float*)d_in[7];
    const float* n1b = (const float*)d_in[8];
    const float* awW = (const float*)d_in[9];
    const float* awb = (const float*)d_in[10];
    const float* soW = (const float*)d_in[11];
    const float* sob = (const float*)d_in[12];
    const float* n2g  = (const float*)d_in[23];
    const float* n2b  = (const float*)d_in[24];
    const float* fc1W = (const float*)d_in[25];
    const float* fc1b = (const float*)d_in[26];
    const float* fc2W = (const float*)d_in[27];
    const float* fc2b = (const float*)d_in[28];
    float* out = (float*)d_out;

    ProjParams P;
    for (int lvl = 0; lvl < 5; lvl++) {
        P.feat[lvl] = (const float*)d_in[2 + lvl];
        P.W[lvl]    = (const float*)d_in[13 + 2 * lvl];
        P.bias[lvl] = (const float*)d_in[14 + 2 * lvl];
    }

    convert_w<<<1920, 256>>>(fc1W, fc2W, P.bias[2], P.bias[3], P.bias[4], x, out);
    proj_all<<<1504, 256>>>(P);
    token_fused<<<2560, 256>>>(x, ref, n1g, n1b, awW, awb, soW, sob, n2g, n2b, out);
    mma_gemm<256, 512, 0><<<dim3(4, 160), 256>>>(fc1b, out);
    mma_gemm<512, 256, 1><<<dim3(2, 160), 256>>>(fc2b, out);
}

// round 15
// speedup vs baseline: 1.4661x; 1.1145x over previous
#include <cuda_runtime.h>
#include <cuda_bf16.h>
#include <math.h>

// ---------------- scratch (static device globals; no allocation) ----------------
static __device__ __align__(16) float g_pfeat[2818048];
static __device__ __align__(16) unsigned g_h2p[20480 * 128];   // LN2 out, K=256 (frag-packed)
static __device__ __align__(16) unsigned g_mlpp[20480 * 256];  // gelu out, K=512 (frag-packed)
static __device__ __align__(16) unsigned g_w1[128 * 512];   // fc1 W frag-packed
static __device__ __align__(16) unsigned g_w2[256 * 256];   // fc2 W frag-packed

__device__ __forceinline__ unsigned pack_bf2(float lo, float hi) {
    __nv_bfloat162 h = __floats2bfloat162_rn(lo, hi);
    return *(unsigned*)&h;
}

// word (row r, k-pair kp) -> index into fragment-packed A array (unsigned units)
__device__ __forceinline__ size_t apack_widx(int r, int kp, int K16) {
    return (((size_t)(r >> 4) * K16 + (kp >> 3)) * 32 + ((r & 7) * 4 + (kp & 3))) * 4
           + (size_t)(((kp >> 2) & 1) * 2 + ((r >> 3) & 1));
}

__device__ __forceinline__ float gelu_exact(float v) {
    return v * (0.5f * (1.0f + erff(v * 0.70710678118654752f)));
}

// ---------------- pre-pack weights + bias-init split pfeat + x0 copy (merged) ----------------
__global__ void convert_w(const float* __restrict__ fc1W, const float* __restrict__ fc2W,
                          const float* __restrict__ ep2b, const float* __restrict__ ep3b,
                          const float* __restrict__ ep4b,
                          const float* __restrict__ x, float* __restrict__ out) {
    int i = blockIdx.x * blockDim.x + threadIdx.x;    // 0..491519
    if (i < 32768) {
        bool is2 = i >= 16384;
        int j = is2 ? i - 16384 : i;
        const float* Wsrc = is2 ? fc2W : fc1W;
        int N = is2 ? 256 : 512;
        int GG = N / 16;
        int lane = j & 31;
        int gg = (j >> 5) % GG;
        int ks = (j >> 5) / GG;
        int gid = lane >> 2, tig = lane & 3;
        int col = gg * 16 + gid;
        int k0 = ks * 16 + 2 * tig;
        uint4 u;
        u.x = pack_bf2(Wsrc[(size_t)(k0 + 0) * N + col],     Wsrc[(size_t)(k0 + 1) * N + col]);
        u.y = pack_bf2(Wsrc[(size_t)(k0 + 8) * N + col],     Wsrc[(size_t)(k0 + 9) * N + col]);
        u.z = pack_bf2(Wsrc[(size_t)(k0 + 0) * N + col + 8], Wsrc[(size_t)(k0 + 1) * N + col + 8]);
        u.w = pack_bf2(Wsrc[(size_t)(k0 + 8) * N + col + 8], Wsrc[(size_t)(k0 + 9) * N + col + 8]);
        ((uint4*)(is2 ? (void*)g_w2 : (void*)g_w1))[j] = u;
    } else if (i < 229376) {
        int idx = i - 32768;               // 0..196607
        const float* bp = (idx < 131072) ? ep2b : (idx < 163840 ? ep3b : ep4b);
        g_pfeat[2621440 + idx] = bp[idx & 31];
    } else {
        int j = i - 229376;
        int b = j >> 16;
        int r = j & 65535;
        size_t off = (size_t)b * (6 * 65536) + r;
        ((float4*)out)[off] = ((const float4*)x)[off];
    }
}

// ---------------- merged feature projection, channel-split for large C ----------------
struct ProjParams {
    const float* feat[5];
    const float* W[5];
    const float* bias[5];
};

__global__ __launch_bounds__(256) void proj_all(ProjParams P) {
    const int starts[6] = {0, 64, 96, 224, 480, 1504};
    const int levs[5]   = {3, 4, 2, 1, 0};
    const int shifts[5] = {2, 1, 1, 0, 0};
    const int Cs[5]   = {64, 128, 256, 512, 256};
    const int HWs[5]  = {16384, 4096, 1024, 256, 256};
    const int offs[5] = {0, 2097152, 2621440, 2752512, 2785280};

    __shared__ float featS[32][64];
    __shared__ float WS[32][32];

    int blk = blockIdx.x;
    int gi = 0;
#pragma unroll
    for (int i = 0; i < 4; i++) if (blk >= starts[gi + 1]) gi++;
    int l = levs[gi];
    int shift = shifts[gi];
    int split = 1 << shift;
    int rel = blk - starts[gi];
    int tile = rel >> shift;
    int s = rel & (split - 1);

    int C = Cs[l], HW = HWs[l];
    int Cper = C >> shift;
    int c_base = s * Cper;
    int pixbase = tile * 64;
    int b = pixbase / HW;
    int idx0 = pixbase - b * HW;

    const float* feat = P.feat[l];
    const float* Wp = P.W[l];
    const float* bp = P.bias[l];

    int t = threadIdx.x;
    int px = t & 63, grp = t >> 6;

    float acc[8];
#pragma unroll
    for (int j = 0; j < 8; j++) acc[j] = (split == 1) ? bp[grp * 8 + j] : 0.0f;

    size_t fbase = ((size_t)b * C) * HW + idx0;

    for (int c0 = c_base; c0 < c_base + Cper; c0 += 32) {
        __syncthreads();
#pragma unroll
        for (int k = 0; k < 8; k++) {
            int j = t + k * 256;
            int cc = j >> 6, pp = j & 63;
            featS[cc][pp] = feat[fbase + (size_t)(c0 + cc) * HW + pp];
        }
#pragma unroll
        for (int k = 0; k < 4; k++) {
            int j = t + k * 256;
            WS[j >> 5][j & 31] = Wp[(size_t)(c0 + (j >> 5)) * 32 + (j & 31)];
        }
        __syncthreads();
#pragma unroll
        for (int cc = 0; cc < 32; cc++) {
            float fv = featS[cc][px];
#pragma unroll
            for (int j = 0; j < 8; j++)
                acc[j] = fmaf(fv, WS[cc][grp * 8 + j], acc[j]);
        }
    }
    float* o = g_pfeat + offs[l] + (size_t)(pixbase + px) * 32 + grp * 8;
    if (split == 1) {
        *(float4*)o = make_float4(acc[0], acc[1], acc[2], acc[3]);
        *(float4*)(o + 4) = make_float4(acc[4], acc[5], acc[6], acc[7]);
    } else {
#pragma unroll
        for (int j = 0; j < 8; j++) atomicAdd(o + j, acc[j]);
    }
}

// ---------------- fused token kernel: 8 tokens per block, 256 threads ----------------
__global__ __launch_bounds__(256) void token_fused(
    const float* __restrict__ x, const float* __restrict__ ref,
    const float* __restrict__ n1g, const float* __restrict__ n1b,
    const float* __restrict__ awW, const float* __restrict__ awb,
    const float* __restrict__ soW, const float* __restrict__ sob,
    const float* __restrict__ n2g, const float* __restrict__ n2b,
    float* __restrict__ out) {
    __shared__ __align__(16) float hT_sh[256][12];
    __shared__ float logit_sh[8][96];
    __shared__ float logit2_sh[8][96];
    __shared__ float aw_sh[8][32];
    __shared__ __align__(16) int   tap_sh[8][32][4];
    __shared__ __align__(16) float wgt_sh[8][32][4];
    __shared__ float o_sh[8][256];

    int t = threadIdx.x, lane = t & 31, w = t >> 5;
    int m0 = blockIdx.x * 8;
    int b = m0 / 5120;
    int lp = m0 - b * 5120;
    int l = lp >> 10;
    int p0 = lp & 1023;
    size_t base_q = ((size_t)(b * 6 + l + 1) * 1024 + p0) * 256;
    size_t base_0 = ((size_t)(b * 6) * 1024 + p0) * 256;

    const int lvlW_[5] = {128, 64, 32, 16, 16};
    const int lvlOff_[5] = {0, 2097152, 2621440, 2752512, 2785280};
    const int W = lvlW_[l];
    const float* lvlbase = g_pfeat + lvlOff_[l] + (size_t)b * W * W * 32;

    // ---- P1: LN1 ----
    {
        size_t xq_off = base_q + (size_t)w * 256;
        size_t x0_off = base_0 + (size_t)w * 256;
        float sv[8];
        float s = 0.0f;
#pragma unroll
        for (int i = 0; i < 8; i++) {
            int c = lane + 32 * i;
            sv[i] = x[xq_off + c] + x[x0_off + c];
            s += sv[i];
        }
#pragma unroll
        for (int o = 16; o > 0; o >>= 1) s += __shfl_xor_sync(0xffffffffu, s, o);
        float mean = s * (1.0f / 256.0f);
        float v = 0.0f;
#pragma unroll
        for (int i = 0; i < 8; i++) { float d = sv[i] - mean; v += d * d; }
#pragma unroll
        for (int o = 16; o > 0; o >>= 1) v += __shfl_xor_sync(0xffffffffu, v, o);
        float rstd = rsqrtf(v * (1.0f / 256.0f) + 1e-5f);
#pragma unroll
        for (int i = 0; i < 8; i++) {
            int c = lane + 32 * i;
            hT_sh[c][w] = (sv[i] - mean) * rstd * n1g[c] + n1b[c];
        }
    }
    __syncthreads();

    // ---- P2: head logits, k-split (192 threads) ----
    if (t < 192) {
        int half = t >= 96;
        int j = t - 96 * half;
        int k0 = half * 128;
        const float* wcol;
        int stride;
        float bias = 0.0f;
        if (j < 32) { wcol = awW + j; stride = 32; if (!half) bias = awb[j]; }
        else        { wcol = soW + (j - 32); stride = 64; if (!half) bias = sob[j - 32]; }
        wcol += (size_t)k0 * stride;
        float acc0 = bias, acc1 = bias, acc2 = bias, acc3 = bias;
        float acc4 = bias, acc5 = bias, acc6 = bias, acc7 = bias;
#pragma unroll 8
        for (int k = 0; k < 128; k++) {
            float wv = __ldg(wcol + (size_t)k * stride);
            float4 hA = *(const float4*)&hT_sh[k0 + k][0];
            float4 hB = *(const float4*)&hT_sh[k0 + k][4];
            acc0 = fmaf(hA.x, wv, acc0);
            acc1 = fmaf(hA.y, wv, acc1);
            acc2 = fmaf(hA.z, wv, acc2);
            acc3 = fmaf(hA.w, wv, acc3);
            acc4 = fmaf(hB.x, wv, acc4);
            acc5 = fmaf(hB.y, wv, acc5);
            acc6 = fmaf(hB.z, wv, acc6);
            acc7 = fmaf(hB.w, wv, acc7);
        }
        float (*dst)[96] = half ? logit2_sh : logit_sh;
        dst[0][j] = acc0; dst[1][j] = acc1;
        dst[2][j] = acc2; dst[3][j] = acc3;
        dst[4][j] = acc4; dst[5][j] = acc5;
        dst[6][j] = acc6; dst[7][j] = acc7;
    }
    __syncthreads();

    // ---- P3a: softmax ----
    if (t < 64) {
        int tok = t >> 3, hd = t & 7;
        float v0 = logit_sh[tok][hd * 4 + 0] + logit2_sh[tok][hd * 4 + 0];
        float v1 = logit_sh[tok][hd * 4 + 1] + logit2_sh[tok][hd * 4 + 1];
        float v2 = logit_sh[tok][hd * 4 + 2] + logit2_sh[tok][hd * 4 + 2];
        float v3 = logit_sh[tok][hd * 4 + 3] + logit2_sh[tok][hd * 4 + 3];
        float mx = fmaxf(fmaxf(v0, v1), fmaxf(v2, v3));
        float e0 = expf(v0 - mx), e1 = expf(v1 - mx), e2 = expf(v2 - mx), e3 = expf(v3 - mx);
        float inv = 1.0f / (e0 + e1 + e2 + e3);
        aw_sh[tok][hd * 4 + 0] = e0 * inv;
        aw_sh[tok][hd * 4 + 1] = e1 * inv;
        aw_sh[tok][hd * 4 + 2] = e2 * inv;
        aw_sh[tok][hd * 4 + 3] = e3 * inv;
    }
    __syncthreads();

    // ---- P3b: taps + combined weights ----
    {
        int tok = t >> 5, q = lane;
        float rx = ref[((size_t)b * 1024 + p0 + tok) * 2 + 0];
        float ry = ref[((size_t)b * 1024 + p0 + tok) * 2 + 1];
        float lx = logit_sh[tok][32 + 2 * q + 0] + logit2_sh[tok][32 + 2 * q + 0];
        float ly = logit_sh[tok][32 + 2 * q + 1] + logit2_sh[tok][32 + 2 * q + 1];
        float px_ = tanhf(lx) + rx;
        float py_ = tanhf(ly) + ry;
        float fw = (float)(W - 1);
        float gx = fminf(fmaxf((px_ + 1.0f) * 0.5f * fw, 0.0f), fw);
        float gy = fminf(fmaxf((py_ + 1.0f) * 0.5f * fw, 0.0f), fw);
        float x0f = floorf(gx), y0f = floorf(gy);
        float wx = gx - x0f, wy = gy - y0f;
        int x0i = (int)x0f, y0i = (int)y0f;
        int x1i = min(x0i + 1, W - 1), y1i = min(y0i + 1, W - 1);
        *(int4*)tap_sh[tok][q] = make_int4((y0i * W + x0i) * 32, (y0i * W + x1i) * 32,
                                           (y1i * W + x0i) * 32, (y1i * W + x1i) * 32);
        float a = aw_sh[tok][q];
        *(float4*)wgt_sh[tok][q] = make_float4(a * (1.0f - wx) * (1.0f - wy),
                                               a * wx * (1.0f - wy),
                                               a * (1.0f - wx) * wy,
                                               a * wx * wy);
    }
    __syncthreads();

    // ---- P4: coalesced gather + head accumulate ----
#pragma unroll
    for (int iter = 0; iter < 2; iter++) {
        int slot = t + 256 * iter;
        int tok = slot >> 6;
        int head = (slot >> 3) & 7;
        int cg = (slot & 7) * 4;
        float ax = 0.0f, ay = 0.0f, az = 0.0f, aw4 = 0.0f;
#pragma unroll
        for (int s = 0; s < 4; s++) {
            int q = head * 4 + s;
            int4 tp = *(const int4*)tap_sh[tok][q];
            float4 wt = *(const float4*)wgt_sh[tok][q];
            float4 f0 = *(const float4*)(lvlbase + tp.x + cg);
            float4 f1 = *(const float4*)(lvlbase + tp.y + cg);
            float4 f2 = *(const float4*)(lvlbase + tp.z + cg);
            float4 f3 = *(const float4*)(lvlbase + tp.w + cg);
            ax = fmaf(wt.x, f0.x, fmaf(wt.y, f1.x, fmaf(wt.z, f2.x, fmaf(wt.w, f3.x, ax))));
            ay = fmaf(wt.x, f0.y, fmaf(wt.y, f1.y, fmaf(wt.z, f2.y, fmaf(wt.w, f3.y, ay))));
            az = fmaf(wt.x, f0.z, fmaf(wt.y, f1.z, fmaf(wt.z, f2.z, fmaf(wt.w, f3.z, az))));
            aw4 = fmaf(wt.x, f0.w, fmaf(wt.y, f1.w, fmaf(wt.z, f2.w, fmaf(wt.w, f3.w, aw4))));
        }
        *(float4*)&o_sh[tok][head * 32 + cg] = make_float4(ax, ay, az, aw4);
    }
    __syncthreads();

    // ---- P5: residual + LN2 -> fragment-packed bf16 h2 ----
    {
        size_t xq_off = base_q + (size_t)w * 256;
        int r = m0 + w;
        float o8[8];
        float s = 0.0f;
#pragma unroll
        for (int i = 0; i < 4; i++) {
            int c0 = 2 * lane + 64 * i;
            float2 xv = *(const float2*)(x + xq_off + c0);
            float v0 = xv.x + o_sh[w][c0];
            float v1 = xv.y + o_sh[w][c0 + 1];
            *(float2*)(out + xq_off + c0) = make_float2(v0, v1);
            o8[2 * i] = v0; o8[2 * i + 1] = v1;
            s += v0 + v1;
        }
#pragma unroll
        for (int o = 16; o > 0; o >>= 1) s += __shfl_xor_sync(0xffffffffu, s, o);
        float mean = s * (1.0f / 256.0f);
        float v = 0.0f;
#pragma unroll
        for (int i = 0; i < 8; i++) { float d = o8[i] - mean; v += d * d; }
#pragma unroll
        for (int o = 16; o > 0; o >>= 1) v += __shfl_xor_sync(0xffffffffu, v, o);
        float rstd = rsqrtf(v * (1.0f / 256.0f) + 1e-5f);
#pragma unroll
        for (int i = 0; i < 4; i++) {
            int c0 = 2 * lane + 64 * i;
            float2 g2 = *(const float2*)(n2g + c0);
            float2 b2 = *(const float2*)(n2b + c0);
            float h0 = (o8[2 * i] - mean) * rstd * g2.x + b2.x;
            float h1 = (o8[2 * i + 1] - mean) * rstd * g2.y + b2.y;
            g_h2p[apack_widx(r, lane + 32 * i, 16)] = pack_bf2(h0, h1);
        }
    }
}

// ---------------- bf16 tensor-core GEMM: no smem, explicit register pipeline ----------------
template <int K, int NDIM, int EPI>
__global__ __launch_bounds__(256) void mma_gemm(const float* __restrict__ bias,
                                                float* __restrict__ out) {
    const uint4* A4 = (EPI == 0) ? (const uint4*)g_h2p : (const uint4*)g_mlpp;
    const uint4* B4 = (EPI == 0) ? (const uint4*)g_w1 : (const uint4*)g_w2;
    const int K16 = K / 16;
    const int GG = NDIM / 16;

    int tid = threadIdx.x;
    int m0 = blockIdx.y * 128, n0 = blockIdx.x * 128;
    int lane = tid & 31, wid = tid >> 5;
    int wm = wid & 3, wn = wid >> 2;
    int gid = lane >> 2, tig = lane & 3;

    int mtile = (m0 + wm * 32) >> 4;
    const uint4* Ap = A4 + ((size_t)mtile * K16) * 32 + lane;
    const uint4* Bp = B4 + ((size_t)(n0 >> 4) + wn * 4) * 32 + lane;
    const size_t bstep = (size_t)GG * 32;

    float acc[2][8][4];
#pragma unroll
    for (int mt = 0; mt < 2; mt++)
#pragma unroll
        for (int nt = 0; nt < 8; nt++)
#pragma unroll
            for (int r = 0; r < 4; r++) acc[mt][nt][r] = 0.0f;

    // prologue loads for ks=0
    uint4 ca0 = __ldg(Ap);
    uint4 ca1 = __ldg(Ap + (size_t)K16 * 32);
    uint4 cb0 = __ldg(Bp);
    uint4 cb1 = __ldg(Bp + 32);
    uint4 cb2 = __ldg(Bp + 64);
    uint4 cb3 = __ldg(Bp + 96);

#pragma unroll 2
    for (int ks = 0; ks < K16; ks++) {
        uint4 na0, na1, nb0, nb1, nb2, nb3;
        if (ks + 1 < K16) {
            na0 = __ldg(Ap + (ks + 1) * 32);
            na1 = __ldg(Ap + (size_t)(K16 + ks + 1) * 32);
            const uint4* bp = Bp + (size_t)(ks + 1) * bstep;
            nb0 = __ldg(bp);
            nb1 = __ldg(bp + 32);
            nb2 = __ldg(bp + 64);
            nb3 = __ldg(bp + 96);
        }
        const uint4 bb[4] = {cb0, cb1, cb2, cb3};
#pragma unroll
        for (int p = 0; p < 4; p++) {
            uint4 q = bb[p];
#pragma unroll
            for (int mt = 0; mt < 2; mt++) {
                uint4 a = mt ? ca1 : ca0;
                asm volatile(
                    "mma.sync.aligned.m16n8k16.row.col.f32.bf16.bf16.f32 "
                    "{%0,%1,%2,%3},{%4,%5,%6,%7},{%8,%9},{%0,%1,%2,%3};"
                    : "+f"(acc[mt][2 * p][0]), "+f"(acc[mt][2 * p][1]),
                      "+f"(acc[mt][2 * p][2]), "+f"(acc[mt][2 * p][3])
                    : "r"(a.x), "r"(a.y), "r"(a.z), "r"(a.w), "r"(q.x), "r"(q.y));
                asm volatile(
                    "mma.sync.aligned.m16n8k16.row.col.f32.bf16.bf16.f32 "
                    "{%0,%1,%2,%3},{%4,%5,%6,%7},{%8,%9},{%0,%1,%2,%3};"
                    : "+f"(acc[mt][2 * p + 1][0]), "+f"(acc[mt][2 * p + 1][1]),
                      "+f"(acc[mt][2 * p + 1][2]), "+f"(acc[mt][2 * p + 1][3])
                    : "r"(a.x), "r"(a.y), "r"(a.z), "r"(a.w), "r"(q.z), "r"(q.w));
            }
        }
        ca0 = na0; ca1 = na1;
        cb0 = nb0; cb1 = nb1; cb2 = nb2; cb3 = nb3;
    }

#pragma unroll
    for (int mt = 0; mt < 2; mt++) {
#pragma unroll
        for (int nt = 0; nt < 8; nt++) {
            int r0 = m0 + wm * 32 + mt * 16 + gid;
            int c = n0 + wn * 64 + nt * 8 + 2 * tig;
            float bv0 = __ldg(bias + c), bv1 = __ldg(bias + c + 1);
            if (EPI == 0) {
                float v0 = acc[mt][nt][0] + bv0, v1 = acc[mt][nt][1] + bv1;
                float v2 = acc[mt][nt][2] + bv0, v3 = acc[mt][nt][3] + bv1;
                uint2 u = make_uint2(pack_bf2(gelu_exact(v0), gelu_exact(v1)),
                                     pack_bf2(gelu_exact(v2), gelu_exact(v3)));
                *(uint2*)&g_mlpp[apack_widx(r0, c >> 1, 32)] = u;
            } else {
#pragma unroll
                for (int half = 0; half < 2; half++) {
                    int row = r0 + half * 8;
                    // b = row/5120 via comparisons (rows < 20480)
                    int bb = (row >= 5120) + (row >= 10240) + (row >= 15360);
                    float* orow = out + (size_t)(row + 1024 * (bb + 1)) * 256 + c;
                    float2 cur = *(float2*)orow;
                    cur.x += acc[mt][nt][half * 2 + 0] + bv0;
                    cur.y += acc[mt][nt][half * 2 + 1] + bv1;
                    *(float2*)orow = cur;
                }
            }
        }
    }
}

// ---------------- launch ----------------
extern "C" void kernel_launch(void* const* d_in, const int* in_sizes, int n_in,
                              void* d_out, int out_size) {
    const float* x    = (const float*)d_in[0];
    const float* ref  = (const float*)d_in[1];
    const float* n1g = (const float*)d_in[7];
    const float* n1b = (const float*)d_in[8];
    const float* awW = (const float*)d_in[9];
    const float* awb = (const float*)d_in[10];
    const float* soW = (const float*)d_in[11];
    const float* sob = (const float*)d_in[12];
    const float* n2g  = (const float*)d_in[23];
    const float* n2b  = (const float*)d_in[24];
    const float* fc1W = (const float*)d_in[25];
    const float* fc1b = (const float*)d_in[26];
    const float* fc2W = (const float*)d_in[27];
    const float* fc2b = (const float*)d_in[28];
    float* out = (float*)d_out;

    ProjParams P;
    for (int lvl = 0; lvl < 5; lvl++) {
        P.feat[lvl] = (const float*)d_in[2 + lvl];
        P.W[lvl]    = (const float*)d_in[13 + 2 * lvl];
        P.bias[lvl] = (const float*)d_in[14 + 2 * lvl];
    }

    convert_w<<<1920, 256>>>(fc1W, fc2W, P.bias[2], P.bias[3], P.bias[4], x, out);
    proj_all<<<1504, 256>>>(P);
    token_fused<<<2560, 256>>>(x, ref, n1g, n1b, awW, awb, soW, sob, n2g, n2b, out);
    mma_gemm<256, 512, 0><<<dim3(4, 160), 256>>>(fc1b, out);
    mma_gemm<512, 256, 1><<<dim3(2, 160), 256>>>(fc2b, out);
}

// round 16
// speedup vs baseline: 1.4803x; 1.0097x over previous
#include <cuda_runtime.h>
#include <cuda_bf16.h>
#include <math.h>

// ---------------- scratch (static device globals; no allocation) ----------------
static __device__ __align__(16) float g_pfeat[2818048];
static __device__ __align__(16) unsigned g_h2p[20480 * 128];   // LN2 out, K=256 (frag-packed)
static __device__ __align__(16) unsigned g_mlpp[20480 * 256];  // gelu out, K=512 (frag-packed)
static __device__ __align__(16) unsigned g_w1[128 * 512];   // fc1 W frag-packed
static __device__ __align__(16) unsigned g_w2[256 * 256];   // fc2 W frag-packed

__device__ __forceinline__ unsigned pack_bf2(float lo, float hi) {
    __nv_bfloat162 h = __floats2bfloat162_rn(lo, hi);
    return *(unsigned*)&h;
}

// word (row r, k-pair kp) -> index into fragment-packed A array (unsigned units)
__device__ __forceinline__ size_t apack_widx(int r, int kp, int K16) {
    return (((size_t)(r >> 4) * K16 + (kp >> 3)) * 32 + ((r & 7) * 4 + (kp & 3))) * 4
           + (size_t)(((kp >> 2) & 1) * 2 + ((r >> 3) & 1));
}

__device__ __forceinline__ float gelu_exact(float v) {
    return v * (0.5f * (1.0f + erff(v * 0.70710678118654752f)));
}

// ---------------- pre-pack weights + bias-init split pfeat + x0 copy (merged) ----------------
__global__ void convert_w(const float* __restrict__ fc1W, const float* __restrict__ fc2W,
                          const float* __restrict__ ep2b, const float* __restrict__ ep3b,
                          const float* __restrict__ ep4b,
                          const float* __restrict__ x, float* __restrict__ out) {
    int i = blockIdx.x * blockDim.x + threadIdx.x;    // 0..491519
    if (i < 32768) {
        bool is2 = i >= 16384;
        int j = is2 ? i - 16384 : i;
        const float* Wsrc = is2 ? fc2W : fc1W;
        int N = is2 ? 256 : 512;
        int GG = N / 16;
        int lane = j & 31;
        int gg = (j >> 5) % GG;
        int ks = (j >> 5) / GG;
        int gid = lane >> 2, tig = lane & 3;
        int col = gg * 16 + gid;
        int k0 = ks * 16 + 2 * tig;
        uint4 u;
        u.x = pack_bf2(Wsrc[(size_t)(k0 + 0) * N + col],     Wsrc[(size_t)(k0 + 1) * N + col]);
        u.y = pack_bf2(Wsrc[(size_t)(k0 + 8) * N + col],     Wsrc[(size_t)(k0 + 9) * N + col]);
        u.z = pack_bf2(Wsrc[(size_t)(k0 + 0) * N + col + 8], Wsrc[(size_t)(k0 + 1) * N + col + 8]);
        u.w = pack_bf2(Wsrc[(size_t)(k0 + 8) * N + col + 8], Wsrc[(size_t)(k0 + 9) * N + col + 8]);
        ((uint4*)(is2 ? (void*)g_w2 : (void*)g_w1))[j] = u;
    } else if (i < 229376) {
        int idx = i - 32768;               // 0..196607
        const float* bp = (idx < 131072) ? ep2b : (idx < 163840 ? ep3b : ep4b);
        g_pfeat[2621440 + idx] = bp[idx & 31];
    } else {
        int j = i - 229376;
        int b = j >> 16;
        int r = j & 65535;
        size_t off = (size_t)b * (6 * 65536) + r;
        ((float4*)out)[off] = ((const float4*)x)[off];
    }
}

// ---------------- merged feature projection, channel-split for large C ----------------
struct ProjParams {
    const float* feat[5];
    const float* W[5];
    const float* bias[5];
};

__global__ __launch_bounds__(256) void proj_all(ProjParams P) {
    const int starts[6] = {0, 64, 96, 224, 480, 1504};
    const int levs[5]   = {3, 4, 2, 1, 0};
    const int shifts[5] = {2, 1, 1, 0, 0};
    const int Cs[5]   = {64, 128, 256, 512, 256};
    const int HWs[5]  = {16384, 4096, 1024, 256, 256};
    const int offs[5] = {0, 2097152, 2621440, 2752512, 2785280};

    __shared__ float featS[32][64];
    __shared__ float WS[32][32];

    int blk = blockIdx.x;
    int gi = 0;
#pragma unroll
    for (int i = 0; i < 4; i++) if (blk >= starts[gi + 1]) gi++;
    int l = levs[gi];
    int shift = shifts[gi];
    int split = 1 << shift;
    int rel = blk - starts[gi];
    int tile = rel >> shift;
    int s = rel & (split - 1);

    int C = Cs[l], HW = HWs[l];
    int Cper = C >> shift;
    int c_base = s * Cper;
    int pixbase = tile * 64;
    int b = pixbase / HW;
    int idx0 = pixbase - b * HW;

    const float* feat = P.feat[l];
    const float* Wp = P.W[l];
    const float* bp = P.bias[l];

    int t = threadIdx.x;
    int px = t & 63, grp = t >> 6;

    float acc[8];
#pragma unroll
    for (int j = 0; j < 8; j++) acc[j] = (split == 1) ? bp[grp * 8 + j] : 0.0f;

    size_t fbase = ((size_t)b * C) * HW + idx0;

    for (int c0 = c_base; c0 < c_base + Cper; c0 += 32) {
        __syncthreads();
#pragma unroll
        for (int k = 0; k < 8; k++) {
            int j = t + k * 256;
            int cc = j >> 6, pp = j & 63;
            featS[cc][pp] = feat[fbase + (size_t)(c0 + cc) * HW + pp];
        }
#pragma unroll
        for (int k = 0; k < 4; k++) {
            int j = t + k * 256;
            WS[j >> 5][j & 31] = Wp[(size_t)(c0 + (j >> 5)) * 32 + (j & 31)];
        }
        __syncthreads();
#pragma unroll
        for (int cc = 0; cc < 32; cc++) {
            float fv = featS[cc][px];
#pragma unroll
            for (int j = 0; j < 8; j++)
                acc[j] = fmaf(fv, WS[cc][grp * 8 + j], acc[j]);
        }
    }
    float* o = g_pfeat + offs[l] + (size_t)(pixbase + px) * 32 + grp * 8;
    if (split == 1) {
        *(float4*)o = make_float4(acc[0], acc[1], acc[2], acc[3]);
        *(float4*)(o + 4) = make_float4(acc[4], acc[5], acc[6], acc[7]);
    } else {
#pragma unroll
        for (int j = 0; j < 8; j++) atomicAdd(o + j, acc[j]);
    }
}

// ---------------- fused token kernel: 8 tokens per block, 256 threads ----------------
__global__ __launch_bounds__(256) void token_fused(
    const float* __restrict__ x, const float* __restrict__ ref,
    const float* __restrict__ n1g, const float* __restrict__ n1b,
    const float* __restrict__ awW, const float* __restrict__ awb,
    const float* __restrict__ soW, const float* __restrict__ sob,
    const float* __restrict__ n2g, const float* __restrict__ n2b,
    float* __restrict__ out) {
    __shared__ __align__(16) float hT_sh[256][12];
    __shared__ float logit_sh[8][96];
    __shared__ float logit2_sh[8][96];
    __shared__ float aw_sh[8][32];
    __shared__ __align__(16) int   tap_sh[8][32][4];
    __shared__ __align__(16) float wgt_sh[8][32][4];
    __shared__ float o_sh[8][256];

    int t = threadIdx.x, lane = t & 31, w = t >> 5;
    int m0 = blockIdx.x * 8;
    int b = m0 / 5120;
    int lp = m0 - b * 5120;
    int l = lp >> 10;
    int p0 = lp & 1023;
    size_t base_q = ((size_t)(b * 6 + l + 1) * 1024 + p0) * 256;
    size_t base_0 = ((size_t)(b * 6) * 1024 + p0) * 256;

    const int lvlW_[5] = {128, 64, 32, 16, 16};
    const int lvlOff_[5] = {0, 2097152, 2621440, 2752512, 2785280};
    const int W = lvlW_[l];
    const float* lvlbase = g_pfeat + lvlOff_[l] + (size_t)b * W * W * 32;

    // ---- P1: LN1 ----
    {
        size_t xq_off = base_q + (size_t)w * 256;
        size_t x0_off = base_0 + (size_t)w * 256;
        float sv[8];
        float s = 0.0f;
#pragma unroll
        for (int i = 0; i < 8; i++) {
            int c = lane + 32 * i;
            sv[i] = x[xq_off + c] + x[x0_off + c];
            s += sv[i];
        }
#pragma unroll
        for (int o = 16; o > 0; o >>= 1) s += __shfl_xor_sync(0xffffffffu, s, o);
        float mean = s * (1.0f / 256.0f);
        float v = 0.0f;
#pragma unroll
        for (int i = 0; i < 8; i++) { float d = sv[i] - mean; v += d * d; }
#pragma unroll
        for (int o = 16; o > 0; o >>= 1) v += __shfl_xor_sync(0xffffffffu, v, o);
        float rstd = rsqrtf(v * (1.0f / 256.0f) + 1e-5f);
#pragma unroll
        for (int i = 0; i < 8; i++) {
            int c = lane + 32 * i;
            hT_sh[c][w] = (sv[i] - mean) * rstd * n1g[c] + n1b[c];
        }
    }
    __syncthreads();

    // ---- P2: head logits, k-split (192 threads) ----
    if (t < 192) {
        int half = t >= 96;
        int j = t - 96 * half;
        int k0 = half * 128;
        const float* wcol;
        int stride;
        float bias = 0.0f;
        if (j < 32) { wcol = awW + j; stride = 32; if (!half) bias = awb[j]; }
        else        { wcol = soW + (j - 32); stride = 64; if (!half) bias = sob[j - 32]; }
        wcol += (size_t)k0 * stride;
        float acc0 = bias, acc1 = bias, acc2 = bias, acc3 = bias;
        float acc4 = bias, acc5 = bias, acc6 = bias, acc7 = bias;
#pragma unroll 8
        for (int k = 0; k < 128; k++) {
            float wv = __ldg(wcol + (size_t)k * stride);
            float4 hA = *(const float4*)&hT_sh[k0 + k][0];
            float4 hB = *(const float4*)&hT_sh[k0 + k][4];
            acc0 = fmaf(hA.x, wv, acc0);
            acc1 = fmaf(hA.y, wv, acc1);
            acc2 = fmaf(hA.z, wv, acc2);
            acc3 = fmaf(hA.w, wv, acc3);
            acc4 = fmaf(hB.x, wv, acc4);
            acc5 = fmaf(hB.y, wv, acc5);
            acc6 = fmaf(hB.z, wv, acc6);
            acc7 = fmaf(hB.w, wv, acc7);
        }
        float (*dst)[96] = half ? logit2_sh : logit_sh;
        dst[0][j] = acc0; dst[1][j] = acc1;
        dst[2][j] = acc2; dst[3][j] = acc3;
        dst[4][j] = acc4; dst[5][j] = acc5;
        dst[6][j] = acc6; dst[7][j] = acc7;
    }
    __syncthreads();

    // ---- P3a: softmax ----
    if (t < 64) {
        int tok = t >> 3, hd = t & 7;
        float v0 = logit_sh[tok][hd * 4 + 0] + logit2_sh[tok][hd * 4 + 0];
        float v1 = logit_sh[tok][hd * 4 + 1] + logit2_sh[tok][hd * 4 + 1];
        float v2 = logit_sh[tok][hd * 4 + 2] + logit2_sh[tok][hd * 4 + 2];
        float v3 = logit_sh[tok][hd * 4 + 3] + logit2_sh[tok][hd * 4 + 3];
        float mx = fmaxf(fmaxf(v0, v1), fmaxf(v2, v3));
        float e0 = expf(v0 - mx), e1 = expf(v1 - mx), e2 = expf(v2 - mx), e3 = expf(v3 - mx);
        float inv = 1.0f / (e0 + e1 + e2 + e3);
        aw_sh[tok][hd * 4 + 0] = e0 * inv;
        aw_sh[tok][hd * 4 + 1] = e1 * inv;
        aw_sh[tok][hd * 4 + 2] = e2 * inv;
        aw_sh[tok][hd * 4 + 3] = e3 * inv;
    }
    __syncthreads();

    // ---- P3b: taps + combined weights ----
    {
        int tok = t >> 5, q = lane;
        float rx = ref[((size_t)b * 1024 + p0 + tok) * 2 + 0];
        float ry = ref[((size_t)b * 1024 + p0 + tok) * 2 + 1];
        float lx = logit_sh[tok][32 + 2 * q + 0] + logit2_sh[tok][32 + 2 * q + 0];
        float ly = logit_sh[tok][32 + 2 * q + 1] + logit2_sh[tok][32 + 2 * q + 1];
        float px_ = tanhf(lx) + rx;
        float py_ = tanhf(ly) + ry;
        float fw = (float)(W - 1);
        float gx = fminf(fmaxf((px_ + 1.0f) * 0.5f * fw, 0.0f), fw);
        float gy = fminf(fmaxf((py_ + 1.0f) * 0.5f * fw, 0.0f), fw);
        float x0f = floorf(gx), y0f = floorf(gy);
        float wx = gx - x0f, wy = gy - y0f;
        int x0i = (int)x0f, y0i = (int)y0f;
        int x1i = min(x0i + 1, W - 1), y1i = min(y0i + 1, W - 1);
        *(int4*)tap_sh[tok][q] = make_int4((y0i * W + x0i) * 32, (y0i * W + x1i) * 32,
                                           (y1i * W + x0i) * 32, (y1i * W + x1i) * 32);
        float a = aw_sh[tok][q];
        *(float4*)wgt_sh[tok][q] = make_float4(a * (1.0f - wx) * (1.0f - wy),
                                               a * wx * (1.0f - wy),
                                               a * (1.0f - wx) * wy,
                                               a * wx * wy);
    }
    __syncthreads();

    // ---- P4: coalesced gather + head accumulate ----
#pragma unroll
    for (int iter = 0; iter < 2; iter++) {
        int slot = t + 256 * iter;
        int tok = slot >> 6;
        int head = (slot >> 3) & 7;
        int cg = (slot & 7) * 4;
        float ax = 0.0f, ay = 0.0f, az = 0.0f, aw4 = 0.0f;
#pragma unroll
        for (int s = 0; s < 4; s++) {
            int q = head * 4 + s;
            int4 tp = *(const int4*)tap_sh[tok][q];
            float4 wt = *(const float4*)wgt_sh[tok][q];
            float4 f0 = *(const float4*)(lvlbase + tp.x + cg);
            float4 f1 = *(const float4*)(lvlbase + tp.y + cg);
            float4 f2 = *(const float4*)(lvlbase + tp.z + cg);
            float4 f3 = *(const float4*)(lvlbase + tp.w + cg);
            ax = fmaf(wt.x, f0.x, fmaf(wt.y, f1.x, fmaf(wt.z, f2.x, fmaf(wt.w, f3.x, ax))));
            ay = fmaf(wt.x, f0.y, fmaf(wt.y, f1.y, fmaf(wt.z, f2.y, fmaf(wt.w, f3.y, ay))));
            az = fmaf(wt.x, f0.z, fmaf(wt.y, f1.z, fmaf(wt.z, f2.z, fmaf(wt.w, f3.z, az))));
            aw4 = fmaf(wt.x, f0.w, fmaf(wt.y, f1.w, fmaf(wt.z, f2.w, fmaf(wt.w, f3.w, aw4))));
        }
        *(float4*)&o_sh[tok][head * 32 + cg] = make_float4(ax, ay, az, aw4);
    }
    __syncthreads();

    // ---- P5: residual + LN2 -> fragment-packed bf16 h2 ----
    {
        size_t xq_off = base_q + (size_t)w * 256;
        int r = m0 + w;
        float o8[8];
        float s = 0.0f;
#pragma unroll
        for (int i = 0; i < 4; i++) {
            int c0 = 2 * lane + 64 * i;
            float2 xv = *(const float2*)(x + xq_off + c0);
            float v0 = xv.x + o_sh[w][c0];
            float v1 = xv.y + o_sh[w][c0 + 1];
            *(float2*)(out + xq_off + c0) = make_float2(v0, v1);
            o8[2 * i] = v0; o8[2 * i + 1] = v1;
            s += v0 + v1;
        }
#pragma unroll
        for (int o = 16; o > 0; o >>= 1) s += __shfl_xor_sync(0xffffffffu, s, o);
        float mean = s * (1.0f / 256.0f);
        float v = 0.0f;
#pragma unroll
        for (int i = 0; i < 8; i++) { float d = o8[i] - mean; v += d * d; }
#pragma unroll
        for (int o = 16; o > 0; o >>= 1) v += __shfl_xor_sync(0xffffffffu, v, o);
        float rstd = rsqrtf(v * (1.0f / 256.0f) + 1e-5f);
#pragma unroll
        for (int i = 0; i < 4; i++) {
            int c0 = 2 * lane + 64 * i;
            float2 g2 = *(const float2*)(n2g + c0);
            float2 b2 = *(const float2*)(n2b + c0);
            float h0 = (o8[2 * i] - mean) * rstd * g2.x + b2.x;
            float h1 = (o8[2 * i + 1] - mean) * rstd * g2.y + b2.y;
            g_h2p[apack_widx(r, lane + 32 * i, 16)] = pack_bf2(h0, h1);
        }
    }
}

// ---------------- bf16 tensor-core GEMM: reg pipeline + smem-staged coalesced epilogue ----------------
template <int K, int NDIM, int EPI>
__global__ __launch_bounds__(256) void mma_gemm(const float* __restrict__ bias,
                                                float* __restrict__ out) {
    const uint4* A4 = (EPI == 0) ? (const uint4*)g_h2p : (const uint4*)g_mlpp;
    const uint4* B4 = (EPI == 0) ? (const uint4*)g_w1 : (const uint4*)g_w2;
    const int K16 = K / 16;
    const int GG = NDIM / 16;

    __shared__ __align__(16) unsigned stage[8448];   // fc1: 8192 frag words; fc2: 64x132 floats

    int tid = threadIdx.x;
    int m0 = blockIdx.y * 128, n0 = blockIdx.x * 128;
    int lane = tid & 31, wid = tid >> 5;
    int wm = wid & 3, wn = wid >> 2;
    int gid = lane >> 2, tig = lane & 3;

    int mtile = (m0 + wm * 32) >> 4;
    const uint4* Ap = A4 + ((size_t)mtile * K16) * 32 + lane;
    const uint4* Bp = B4 + ((size_t)(n0 >> 4) + wn * 4) * 32 + lane;
    const size_t bstep = (size_t)GG * 32;

    float acc[2][8][4];
#pragma unroll
    for (int mt = 0; mt < 2; mt++)
#pragma unroll
        for (int nt = 0; nt < 8; nt++)
#pragma unroll
            for (int r = 0; r < 4; r++) acc[mt][nt][r] = 0.0f;

    // prologue loads for ks=0
    uint4 ca0 = __ldg(Ap);
    uint4 ca1 = __ldg(Ap + (size_t)K16 * 32);
    uint4 cb0 = __ldg(Bp);
    uint4 cb1 = __ldg(Bp + 32);
    uint4 cb2 = __ldg(Bp + 64);
    uint4 cb3 = __ldg(Bp + 96);

#pragma unroll 2
    for (int ks = 0; ks < K16; ks++) {
        uint4 na0, na1, nb0, nb1, nb2, nb3;
        if (ks + 1 < K16) {
            na0 = __ldg(Ap + (ks + 1) * 32);
            na1 = __ldg(Ap + (size_t)(K16 + ks + 1) * 32);
            const uint4* bp = Bp + (size_t)(ks + 1) * bstep;
            nb0 = __ldg(bp);
            nb1 = __ldg(bp + 32);
            nb2 = __ldg(bp + 64);
            nb3 = __ldg(bp + 96);
        }
        const uint4 bb[4] = {cb0, cb1, cb2, cb3};
#pragma unroll
        for (int p = 0; p < 4; p++) {
            uint4 q = bb[p];
#pragma unroll
            for (int mt = 0; mt < 2; mt++) {
                uint4 a = mt ? ca1 : ca0;
                asm volatile(
                    "mma.sync.aligned.m16n8k16.row.col.f32.bf16.bf16.f32 "
                    "{%0,%1,%2,%3},{%4,%5,%6,%7},{%8,%9},{%0,%1,%2,%3};"
                    : "+f"(acc[mt][2 * p][0]), "+f"(acc[mt][2 * p][1]),
                      "+f"(acc[mt][2 * p][2]), "+f"(acc[mt][2 * p][3])
                    : "r"(a.x), "r"(a.y), "r"(a.z), "r"(a.w), "r"(q.x), "r"(q.y));
                asm volatile(
                    "mma.sync.aligned.m16n8k16.row.col.f32.bf16.bf16.f32 "
                    "{%0,%1,%2,%3},{%4,%5,%6,%7},{%8,%9},{%0,%1,%2,%3};"
                    : "+f"(acc[mt][2 * p + 1][0]), "+f"(acc[mt][2 * p + 1][1]),
                      "+f"(acc[mt][2 * p + 1][2]), "+f"(acc[mt][2 * p + 1][3])
                    : "r"(a.x), "r"(a.y), "r"(a.z), "r"(a.w), "r"(q.z), "r"(q.w));
            }
        }
        ca0 = na0; ca1 = na1;
        cb0 = nb0; cb1 = nb1; cb2 = nb2; cb3 = nb3;
    }

    if (EPI == 0) {
        // ---- stage frag-packed words in smem, then coalesced uint4 stream to g_mlpp ----
#pragma unroll
        for (int mt = 0; mt < 2; mt++) {
#pragma unroll
            for (int nt = 0; nt < 8; nt++) {
                int c = n0 + wn * 64 + nt * 8 + 2 * tig;
                float bv0 = __ldg(bias + c), bv1 = __ldg(bias + c + 1);
                float v0 = acc[mt][nt][0] + bv0, v1 = acc[mt][nt][1] + bv1;
                float v2 = acc[mt][nt][2] + bv0, v3 = acc[mt][nt][3] + bv1;
                int mti = wm * 2 + mt;
                int ksloc = wn * 4 + (nt >> 1);
                int widx = ((mti * 8 + ksloc) * 32 + lane) * 4 + (nt & 1) * 2;
                uint2 u = make_uint2(pack_bf2(gelu_exact(v0), gelu_exact(v1)),
                                     pack_bf2(gelu_exact(v2), gelu_exact(v3)));
                *(uint2*)&stage[widx] = u;
            }
        }
        __syncthreads();
        uint4* dst = (uint4*)g_mlpp;
        const uint4* src = (const uint4*)stage;
        int mtile0 = m0 >> 4, ks0 = n0 >> 4;
#pragma unroll
        for (int i = 0; i < 8; i++) {
            int j = tid + 256 * i;       // 0..2047
            int mti = j >> 8, ks = (j >> 5) & 7, ln = j & 31;
            dst[((size_t)(mtile0 + mti) * 32 + ks0 + ks) * 32 + ln] = src[j];
        }
    } else {
        // ---- stage fp32 rows in smem, then coalesced float4 RMW of out (2 passes) ----
        float* ep = (float*)stage;       // [64][132]
#pragma unroll
        for (int mt = 0; mt < 2; mt++) {
            __syncthreads();
#pragma unroll
            for (int nt = 0; nt < 8; nt++) {
                int c = wn * 64 + nt * 8 + 2 * tig;
                float bv0 = __ldg(bias + n0 + c), bv1 = __ldg(bias + n0 + c + 1);
#pragma unroll
                for (int half = 0; half < 2; half++) {
                    int rloc = wm * 16 + gid + half * 8;
                    ep[rloc * 132 + c]     = acc[mt][nt][half * 2 + 0] + bv0;
                    ep[rloc * 132 + c + 1] = acc[mt][nt][half * 2 + 1] + bv1;
                }
            }
            __syncthreads();
#pragma unroll
            for (int i = 0; i < 8; i++) {
                int j = tid + 256 * i;   // 0..2047
                int row = j >> 5, cq = j & 31;
                int grow = m0 + (row >> 4) * 32 + mt * 16 + (row & 15);
                int bb = (grow >= 5120) + (grow >= 10240) + (grow >= 15360);
                float* orow = out + (size_t)(grow + 1024 * (bb + 1)) * 256 + n0 + cq * 4;
                float4 cur = *(float4*)orow;
                const float* sp = &ep[row * 132 + cq * 4];
                cur.x += sp[0]; cur.y += sp[1]; cur.z += sp[2]; cur.w += sp[3];
                *(float4*)orow = cur;
            }
        }
    }
}

// ---------------- launch ----------------
extern "C" void kernel_launch(void* const* d_in, const int* in_sizes, int n_in,
                              void* d_out, int out_size) {
    const float* x    = (const float*)d_in[0];
    const float* ref  = (const float*)d_in[1];
    const float* n1g = (const float*)d_in[7];
    const float* n1b = (const float*)d_in[8];
    const float* awW = (const float*)d_in[9];
    const float* awb = (const float*)d_in[10];
    const float* soW = (const float*)d_in[11];
    const float* sob = (const float*)d_in[12];
    const float* n2g  = (const float*)d_in[23];
    const float* n2b  = (const float*)d_in[24];
    const float* fc1W = (const float*)d_in[25];
    const float* fc1b = (const float*)d_in[26];
    const float* fc2W = (const float*)d_in[27];
    const float* fc2b = (const float*)d_in[28];
    float* out = (float*)d_out;

    ProjParams P;
    for (int lvl = 0; lvl < 5; lvl++) {
        P.feat[lvl] = (const float*)d_in[2 + lvl];
        P.W[lvl]    = (const float*)d_in[13 + 2 * lvl];
        P.bias[lvl] = (const float*)d_in[14 + 2 * lvl];
    }

    convert_w<<<1920, 256>>>(fc1W, fc2W, P.bias[2], P.bias[3], P.bias[4], x, out);
    proj_all<<<1504, 256>>>(P);
    token_fused<<<2560, 256>>>(x, ref, n1g, n1b, awW, awb, soW, sob, n2g, n2b, out);
    mma_gemm<256, 512, 0><<<dim3(4, 160), 256>>>(fc1b, out);
    mma_gemm<512, 256, 1><<<dim3(2, 160), 256>>>(fc2b, out);
}

// round 17
// speedup vs baseline: 1.5572x; 1.0519x over previous
#include <cuda_runtime.h>
#include <cuda_bf16.h>
#include <math.h>

// ---------------- scratch (static device globals; no allocation) ----------------
static __device__ __align__(16) float g_pfeat[2818048];
static __device__ __align__(16) unsigned g_h2p[20480 * 128];   // LN2 out, K=256 (frag-packed)
static __device__ __align__(16) unsigned g_mlpp[20480 * 256];  // gelu out, K=512 (frag-packed)
static __device__ __align__(16) unsigned g_w1[128 * 512];   // fc1 W frag-packed
static __device__ __align__(16) unsigned g_w2[256 * 256];   // fc2 W frag-packed

__device__ __forceinline__ unsigned pack_bf2(float lo, float hi) {
    __nv_bfloat162 h = __floats2bfloat162_rn(lo, hi);
    return *(unsigned*)&h;
}

// word (row r, k-pair kp) -> index into fragment-packed A array (unsigned units)
__device__ __forceinline__ size_t apack_widx(int r, int kp, int K16) {
    return (((size_t)(r >> 4) * K16 + (kp >> 3)) * 32 + ((r & 7) * 4 + (kp & 3))) * 4
           + (size_t)(((kp >> 2) & 1) * 2 + ((r >> 3) & 1));
}

__device__ __forceinline__ float gelu_exact(float v) {
    return v * (0.5f * (1.0f + erff(v * 0.70710678118654752f)));
}

// ---------------- pre-pack weights + bias-init split pfeat + x0 copy (merged) ----------------
__global__ void convert_w(const float* __restrict__ fc1W, const float* __restrict__ fc2W,
                          const float* __restrict__ ep2b, const float* __restrict__ ep3b,
                          const float* __restrict__ ep4b,
                          const float* __restrict__ x, float* __restrict__ out) {
    int i = blockIdx.x * blockDim.x + threadIdx.x;    // 0..491519
    if (i < 32768) {
        bool is2 = i >= 16384;
        int j = is2 ? i - 16384 : i;
        const float* Wsrc = is2 ? fc2W : fc1W;
        int N = is2 ? 256 : 512;
        int GG = N / 16;
        int lane = j & 31;
        int gg = (j >> 5) % GG;
        int ks = (j >> 5) / GG;
        int gid = lane >> 2, tig = lane & 3;
        int col = gg * 16 + gid;
        int k0 = ks * 16 + 2 * tig;
        uint4 u;
        u.x = pack_bf2(Wsrc[(size_t)(k0 + 0) * N + col],     Wsrc[(size_t)(k0 + 1) * N + col]);
        u.y = pack_bf2(Wsrc[(size_t)(k0 + 8) * N + col],     Wsrc[(size_t)(k0 + 9) * N + col]);
        u.z = pack_bf2(Wsrc[(size_t)(k0 + 0) * N + col + 8], Wsrc[(size_t)(k0 + 1) * N + col + 8]);
        u.w = pack_bf2(Wsrc[(size_t)(k0 + 8) * N + col + 8], Wsrc[(size_t)(k0 + 9) * N + col + 8]);
        ((uint4*)(is2 ? (void*)g_w2 : (void*)g_w1))[j] = u;
    } else if (i < 229376) {
        int idx = i - 32768;               // 0..196607
        const float* bp = (idx < 131072) ? ep2b : (idx < 163840 ? ep3b : ep4b);
        g_pfeat[2621440 + idx] = bp[idx & 31];
    } else {
        int j = i - 229376;
        int b = j >> 16;
        int r = j & 65535;
        size_t off = (size_t)b * (6 * 65536) + r;
        ((float4*)out)[off] = ((const float4*)x)[off];
    }
}

// ---------------- merged feature projection, channel-split for large C ----------------
struct ProjParams {
    const float* feat[5];
    const float* W[5];
    const float* bias[5];
};

__global__ __launch_bounds__(256) void proj_all(ProjParams P) {
    const int starts[6] = {0, 64, 96, 224, 480, 1504};
    const int levs[5]   = {3, 4, 2, 1, 0};
    const int shifts[5] = {2, 1, 1, 0, 0};
    const int Cs[5]   = {64, 128, 256, 512, 256};
    const int HWs[5]  = {16384, 4096, 1024, 256, 256};
    const int offs[5] = {0, 2097152, 2621440, 2752512, 2785280};

    __shared__ float featS[32][64];
    __shared__ float WS[32][32];

    int blk = blockIdx.x;
    int gi = 0;
#pragma unroll
    for (int i = 0; i < 4; i++) if (blk >= starts[gi + 1]) gi++;
    int l = levs[gi];
    int shift = shifts[gi];
    int split = 1 << shift;
    int rel = blk - starts[gi];
    int tile = rel >> shift;
    int s = rel & (split - 1);

    int C = Cs[l], HW = HWs[l];
    int Cper = C >> shift;
    int c_base = s * Cper;
    int pixbase = tile * 64;
    int b = pixbase / HW;
    int idx0 = pixbase - b * HW;

    const float* feat = P.feat[l];
    const float* Wp = P.W[l];
    const float* bp = P.bias[l];

    int t = threadIdx.x;
    int px = t & 63, grp = t >> 6;

    float acc[8];
#pragma unroll
    for (int j = 0; j < 8; j++) acc[j] = (split == 1) ? bp[grp * 8 + j] : 0.0f;

    size_t fbase = ((size_t)b * C) * HW + idx0;

    for (int c0 = c_base; c0 < c_base + Cper; c0 += 32) {
        __syncthreads();
#pragma unroll
        for (int k = 0; k < 8; k++) {
            int j = t + k * 256;
            int cc = j >> 6, pp = j & 63;
            featS[cc][pp] = feat[fbase + (size_t)(c0 + cc) * HW + pp];
        }
#pragma unroll
        for (int k = 0; k < 4; k++) {
            int j = t + k * 256;
            WS[j >> 5][j & 31] = Wp[(size_t)(c0 + (j >> 5)) * 32 + (j & 31)];
        }
        __syncthreads();
#pragma unroll
        for (int cc = 0; cc < 32; cc++) {
            float fv = featS[cc][px];
#pragma unroll
            for (int j = 0; j < 8; j++)
                acc[j] = fmaf(fv, WS[cc][grp * 8 + j], acc[j]);
        }
    }
    float* o = g_pfeat + offs[l] + (size_t)(pixbase + px) * 32 + grp * 8;
    if (split == 1) {
        *(float4*)o = make_float4(acc[0], acc[1], acc[2], acc[3]);
        *(float4*)(o + 4) = make_float4(acc[4], acc[5], acc[6], acc[7]);
    } else {
#pragma unroll
        for (int j = 0; j < 8; j++) atomicAdd(o + j, acc[j]);
    }
}

// ---------------- fused token kernel: 16 tokens per block, 256 threads ----------------
__global__ __launch_bounds__(256) void token_fused(
    const float* __restrict__ x, const float* __restrict__ ref,
    const float* __restrict__ n1g, const float* __restrict__ n1b,
    const float* __restrict__ awW, const float* __restrict__ awb,
    const float* __restrict__ soW, const float* __restrict__ sob,
    const float* __restrict__ n2g, const float* __restrict__ n2b,
    float* __restrict__ out) {
    // shA: hT[k][tok] stride 20 (20KB) in P1-P2, reused as o_sh[16][256] (16KB) in P4-P5
    __shared__ __align__(16) float shA[256 * 20];
    __shared__ float logit_sh[16][96];             // 6KB
    __shared__ float logit2_sh[16][96];            // 6KB
    __shared__ float aw_sh[16][32];                // 2KB
    __shared__ __align__(16) int   tap_sh[16][32][4];  // 8KB
    __shared__ __align__(16) float wgt_sh[16][32][4];  // 8KB

    int t = threadIdx.x, lane = t & 31, w = t >> 5;
    int m0 = blockIdx.x * 16;
    int b = m0 / 5120;
    int lp = m0 - b * 5120;
    int l = lp >> 10;
    int p0 = lp & 1023;
    size_t base_q = ((size_t)(b * 6 + l + 1) * 1024 + p0) * 256;
    size_t base_0 = ((size_t)(b * 6) * 1024 + p0) * 256;

    const int lvlW_[5] = {128, 64, 32, 16, 16};
    const int lvlOff_[5] = {0, 2097152, 2621440, 2752512, 2785280};
    const int W = lvlW_[l];
    const float* lvlbase = g_pfeat + lvlOff_[l] + (size_t)b * W * W * 32;

    // ---- P1: LN1; warp w handles tokens w and w+8 ----
#pragma unroll
    for (int pass = 0; pass < 2; pass++) {
        int tok = w + 8 * pass;
        size_t xq_off = base_q + (size_t)tok * 256;
        size_t x0_off = base_0 + (size_t)tok * 256;
        float sv[8];
        float s = 0.0f;
#pragma unroll
        for (int i = 0; i < 8; i++) {
            int c = lane + 32 * i;
            sv[i] = x[xq_off + c] + x[x0_off + c];
            s += sv[i];
        }
#pragma unroll
        for (int o = 16; o > 0; o >>= 1) s += __shfl_xor_sync(0xffffffffu, s, o);
        float mean = s * (1.0f / 256.0f);
        float v = 0.0f;
#pragma unroll
        for (int i = 0; i < 8; i++) { float d = sv[i] - mean; v += d * d; }
#pragma unroll
        for (int o = 16; o > 0; o >>= 1) v += __shfl_xor_sync(0xffffffffu, v, o);
        float rstd = rsqrtf(v * (1.0f / 256.0f) + 1e-5f);
#pragma unroll
        for (int i = 0; i < 8; i++) {
            int c = lane + 32 * i;
            shA[c * 20 + tok] = (sv[i] - mean) * rstd * n1g[c] + n1b[c];
        }
    }
    __syncthreads();

    // ---- P2: head logits, k-split (192 threads); 1 weight LDG feeds 16 tokens ----
    if (t < 192) {
        int half = t >= 96;
        int j = t - 96 * half;
        int k0 = half * 128;
        const float* wcol;
        int stride;
        float bias = 0.0f;
        if (j < 32) { wcol = awW + j; stride = 32; if (!half) bias = awb[j]; }
        else        { wcol = soW + (j - 32); stride = 64; if (!half) bias = sob[j - 32]; }
        wcol += (size_t)k0 * stride;
        float acc[16];
#pragma unroll
        for (int i = 0; i < 16; i++) acc[i] = bias;
#pragma unroll 4
        for (int k = 0; k < 128; k++) {
            float wv = __ldg(wcol + (size_t)k * stride);
            const float* hp = &shA[(k0 + k) * 20];
            float4 h0 = *(const float4*)(hp + 0);
            float4 h1 = *(const float4*)(hp + 4);
            float4 h2 = *(const float4*)(hp + 8);
            float4 h3 = *(const float4*)(hp + 12);
            acc[0] = fmaf(h0.x, wv, acc[0]);  acc[1] = fmaf(h0.y, wv, acc[1]);
            acc[2] = fmaf(h0.z, wv, acc[2]);  acc[3] = fmaf(h0.w, wv, acc[3]);
            acc[4] = fmaf(h1.x, wv, acc[4]);  acc[5] = fmaf(h1.y, wv, acc[5]);
            acc[6] = fmaf(h1.z, wv, acc[6]);  acc[7] = fmaf(h1.w, wv, acc[7]);
            acc[8] = fmaf(h2.x, wv, acc[8]);  acc[9] = fmaf(h2.y, wv, acc[9]);
            acc[10] = fmaf(h2.z, wv, acc[10]); acc[11] = fmaf(h2.w, wv, acc[11]);
            acc[12] = fmaf(h3.x, wv, acc[12]); acc[13] = fmaf(h3.y, wv, acc[13]);
            acc[14] = fmaf(h3.z, wv, acc[14]); acc[15] = fmaf(h3.w, wv, acc[15]);
        }
        float (*dst)[96] = half ? logit2_sh : logit_sh;
#pragma unroll
        for (int i = 0; i < 16; i++) dst[i][j] = acc[i];
    }
    __syncthreads();

    // ---- P3a: softmax over NS=4 per head (128 threads) ----
    if (t < 128) {
        int tok = t >> 3, hd = t & 7;
        float v0 = logit_sh[tok][hd * 4 + 0] + logit2_sh[tok][hd * 4 + 0];
        float v1 = logit_sh[tok][hd * 4 + 1] + logit2_sh[tok][hd * 4 + 1];
        float v2 = logit_sh[tok][hd * 4 + 2] + logit2_sh[tok][hd * 4 + 2];
        float v3 = logit_sh[tok][hd * 4 + 3] + logit2_sh[tok][hd * 4 + 3];
        float mx = fmaxf(fmaxf(v0, v1), fmaxf(v2, v3));
        float e0 = expf(v0 - mx), e1 = expf(v1 - mx), e2 = expf(v2 - mx), e3 = expf(v3 - mx);
        float inv = 1.0f / (e0 + e1 + e2 + e3);
        aw_sh[tok][hd * 4 + 0] = e0 * inv;
        aw_sh[tok][hd * 4 + 1] = e1 * inv;
        aw_sh[tok][hd * 4 + 2] = e2 * inv;
        aw_sh[tok][hd * 4 + 3] = e3 * inv;
    }
    __syncthreads();

    // ---- P3b: taps + combined weights (512 slots, 2 iters) ----
#pragma unroll
    for (int it = 0; it < 2; it++) {
        int slot = t + 256 * it;
        int tok = slot >> 5, q = slot & 31;
        float rx = ref[((size_t)b * 1024 + p0 + tok) * 2 + 0];
        float ry = ref[((size_t)b * 1024 + p0 + tok) * 2 + 1];
        float lx = logit_sh[tok][32 + 2 * q + 0] + logit2_sh[tok][32 + 2 * q + 0];
        float ly = logit_sh[tok][32 + 2 * q + 1] + logit2_sh[tok][32 + 2 * q + 1];
        float px_ = tanhf(lx) + rx;
        float py_ = tanhf(ly) + ry;
        float fw = (float)(W - 1);
        float gx = fminf(fmaxf((px_ + 1.0f) * 0.5f * fw, 0.0f), fw);
        float gy = fminf(fmaxf((py_ + 1.0f) * 0.5f * fw, 0.0f), fw);
        float x0f = floorf(gx), y0f = floorf(gy);
        float wx = gx - x0f, wy = gy - y0f;
        int x0i = (int)x0f, y0i = (int)y0f;
        int x1i = min(x0i + 1, W - 1), y1i = min(y0i + 1, W - 1);
        *(int4*)tap_sh[tok][q] = make_int4((y0i * W + x0i) * 32, (y0i * W + x1i) * 32,
                                           (y1i * W + x0i) * 32, (y1i * W + x1i) * 32);
        float a = aw_sh[tok][q];
        *(float4*)wgt_sh[tok][q] = make_float4(a * (1.0f - wx) * (1.0f - wy),
                                               a * wx * (1.0f - wy),
                                               a * (1.0f - wx) * wy,
                                               a * wx * wy);
    }
    __syncthreads();

    // ---- P4: coalesced gather + head accumulate (1024 slots, 4 iters); o overlays hT ----
    float* o_sh = shA;                   // [tok][256]
#pragma unroll
    for (int iter = 0; iter < 4; iter++) {
        int slot = t + 256 * iter;
        int tok = slot >> 6;
        int head = (slot >> 3) & 7;
        int cg = (slot & 7) * 4;
        float ax = 0.0f, ay = 0.0f, az = 0.0f, aw4 = 0.0f;
#pragma unroll
        for (int s = 0; s < 4; s++) {
            int q = head * 4 + s;
            int4 tp = *(const int4*)tap_sh[tok][q];
            float4 wt = *(const float4*)wgt_sh[tok][q];
            float4 f0 = *(const float4*)(lvlbase + tp.x + cg);
            float4 f1 = *(const float4*)(lvlbase + tp.y + cg);
            float4 f2 = *(const float4*)(lvlbase + tp.z + cg);
            float4 f3 = *(const float4*)(lvlbase + tp.w + cg);
            ax = fmaf(wt.x, f0.x, fmaf(wt.y, f1.x, fmaf(wt.z, f2.x, fmaf(wt.w, f3.x, ax))));
            ay = fmaf(wt.x, f0.y, fmaf(wt.y, f1.y, fmaf(wt.z, f2.y, fmaf(wt.w, f3.y, ay))));
            az = fmaf(wt.x, f0.z, fmaf(wt.y, f1.z, fmaf(wt.z, f2.z, fmaf(wt.w, f3.z, az))));
            aw4 = fmaf(wt.x, f0.w, fmaf(wt.y, f1.w, fmaf(wt.z, f2.w, fmaf(wt.w, f3.w, aw4))));
        }
        *(float4*)&o_sh[tok * 256 + head * 32 + cg] = make_float4(ax, ay, az, aw4);
    }
    __syncthreads();

    // ---- P5: residual + LN2 -> fragment-packed bf16 h2; warp w: tokens w, w+8 ----
#pragma unroll
    for (int pass = 0; pass < 2; pass++) {
        int tok = w + 8 * pass;
        size_t xq_off = base_q + (size_t)tok * 256;
        int r = m0 + tok;
        float o8[8];
        float s = 0.0f;
#pragma unroll
        for (int i = 0; i < 4; i++) {
            int c0 = 2 * lane + 64 * i;
            float2 xv = *(const float2*)(x + xq_off + c0);
            float v0 = xv.x + o_sh[tok * 256 + c0];
            float v1 = xv.y + o_sh[tok * 256 + c0 + 1];
            *(float2*)(out + xq_off + c0) = make_float2(v0, v1);
            o8[2 * i] = v0; o8[2 * i + 1] = v1;
            s += v0 + v1;
        }
#pragma unroll
        for (int o = 16; o > 0; o >>= 1) s += __shfl_xor_sync(0xffffffffu, s, o);
        float mean = s * (1.0f / 256.0f);
        float v = 0.0f;
#pragma unroll
        for (int i = 0; i < 8; i++) { float d = o8[i] - mean; v += d * d; }
#pragma unroll
        for (int o = 16; o > 0; o >>= 1) v += __shfl_xor_sync(0xffffffffu, v, o);
        float rstd = rsqrtf(v * (1.0f / 256.0f) + 1e-5f);
#pragma unroll
        for (int i = 0; i < 4; i++) {
            int c0 = 2 * lane + 64 * i;
            float2 g2 = *(const float2*)(n2g + c0);
            float2 b2 = *(const float2*)(n2b + c0);
            float h0 = (o8[2 * i] - mean) * rstd * g2.x + b2.x;
            float h1 = (o8[2 * i + 1] - mean) * rstd * g2.y + b2.y;
            g_h2p[apack_widx(r, lane + 32 * i, 16)] = pack_bf2(h0, h1);
        }
    }
}

// ---------------- bf16 tensor-core GEMM: reg pipeline; fc1 direct epilogue, fc2 staged ----------------
template <int K, int NDIM, int EPI>
__global__ __launch_bounds__(256) void mma_gemm(const float* __restrict__ bias,
                                                float* __restrict__ out) {
    const uint4* A4 = (EPI == 0) ? (const uint4*)g_h2p : (const uint4*)g_mlpp;
    const uint4* B4 = (EPI == 0) ? (const uint4*)g_w1 : (const uint4*)g_w2;
    const int K16 = K / 16;
    const int GG = NDIM / 16;

    __shared__ __align__(16) float stage[(EPI == 1) ? 8448 : 1];

    int tid = threadIdx.x;
    int m0 = blockIdx.y * 128, n0 = blockIdx.x * 128;
    int lane = tid & 31, wid = tid >> 5;
    int wm = wid & 3, wn = wid >> 2;
    int gid = lane >> 2, tig = lane & 3;

    int mtile = (m0 + wm * 32) >> 4;
    const uint4* Ap = A4 + ((size_t)mtile * K16) * 32 + lane;
    const uint4* Bp = B4 + ((size_t)(n0 >> 4) + wn * 4) * 32 + lane;
    const size_t bstep = (size_t)GG * 32;

    float acc[2][8][4];
#pragma unroll
    for (int mt = 0; mt < 2; mt++)
#pragma unroll
        for (int nt = 0; nt < 8; nt++)
#pragma unroll
            for (int r = 0; r < 4; r++) acc[mt][nt][r] = 0.0f;

    uint4 ca0 = __ldg(Ap);
    uint4 ca1 = __ldg(Ap + (size_t)K16 * 32);
    uint4 cb0 = __ldg(Bp);
    uint4 cb1 = __ldg(Bp + 32);
    uint4 cb2 = __ldg(Bp + 64);
    uint4 cb3 = __ldg(Bp + 96);

#pragma unroll 2
    for (int ks = 0; ks < K16; ks++) {
        uint4 na0, na1, nb0, nb1, nb2, nb3;
        if (ks + 1 < K16) {
            na0 = __ldg(Ap + (ks + 1) * 32);
            na1 = __ldg(Ap + (size_t)(K16 + ks + 1) * 32);
            const uint4* bp = Bp + (size_t)(ks + 1) * bstep;
            nb0 = __ldg(bp);
            nb1 = __ldg(bp + 32);
            nb2 = __ldg(bp + 64);
            nb3 = __ldg(bp + 96);
        }
        const uint4 bb[4] = {cb0, cb1, cb2, cb3};
#pragma unroll
        for (int p = 0; p < 4; p++) {
            uint4 q = bb[p];
#pragma unroll
            for (int mt = 0; mt < 2; mt++) {
                uint4 a = mt ? ca1 : ca0;
                asm volatile(
                    "mma.sync.aligned.m16n8k16.row.col.f32.bf16.bf16.f32 "
                    "{%0,%1,%2,%3},{%4,%5,%6,%7},{%8,%9},{%0,%1,%2,%3};"
                    : "+f"(acc[mt][2 * p][0]), "+f"(acc[mt][2 * p][1]),
                      "+f"(acc[mt][2 * p][2]), "+f"(acc[mt][2 * p][3])
                    : "r"(a.x), "r"(a.y), "r"(a.z), "r"(a.w), "r"(q.x), "r"(q.y));
                asm volatile(
                    "mma.sync.aligned.m16n8k16.row.col.f32.bf16.bf16.f32 "
                    "{%0,%1,%2,%3},{%4,%5,%6,%7},{%8,%9},{%0,%1,%2,%3};"
                    : "+f"(acc[mt][2 * p + 1][0]), "+f"(acc[mt][2 * p + 1][1]),
                      "+f"(acc[mt][2 * p + 1][2]), "+f"(acc[mt][2 * p + 1][3])
                    : "r"(a.x), "r"(a.y), "r"(a.z), "r"(a.w), "r"(q.z), "r"(q.w));
            }
        }
        ca0 = na0; ca1 = na1;
        cb0 = nb0; cb1 = nb1; cb2 = nb2; cb3 = nb3;
    }

    if (EPI == 0) {
        // direct scatter (R14 winner)
#pragma unroll
        for (int mt = 0; mt < 2; mt++) {
#pragma unroll
            for (int nt = 0; nt < 8; nt++) {
                int r0 = m0 + wm * 32 + mt * 16 + gid;
                int c = n0 + wn * 64 + nt * 8 + 2 * tig;
                float bv0 = __ldg(bias + c), bv1 = __ldg(bias + c + 1);
                float v0 = acc[mt][nt][0] + bv0, v1 = acc[mt][nt][1] + bv1;
                float v2 = acc[mt][nt][2] + bv0, v3 = acc[mt][nt][3] + bv1;
                uint2 u = make_uint2(pack_bf2(gelu_exact(v0), gelu_exact(v1)),
                                     pack_bf2(gelu_exact(v2), gelu_exact(v3)));
                *(uint2*)&g_mlpp[apack_widx(r0, c >> 1, 32)] = u;
            }
        }
    } else {
        // staged coalesced RMW of out (2 passes)
        float* ep = stage;               // [64][132]
#pragma unroll
        for (int mt = 0; mt < 2; mt++) {
            __syncthreads();
#pragma unroll
            for (int nt = 0; nt < 8; nt++) {
                int c = wn * 64 + nt * 8 + 2 * tig;
                float bv0 = __ldg(bias + n0 + c), bv1 = __ldg(bias + n0 + c + 1);
#pragma unroll
                for (int half = 0; half < 2; half++) {
                    int rloc = wm * 16 + gid + half * 8;
                    ep[rloc * 132 + c]     = acc[mt][nt][half * 2 + 0] + bv0;
                    ep[rloc * 132 + c + 1] = acc[mt][nt][half * 2 + 1] + bv1;
                }
            }
            __syncthreads();
#pragma unroll
            for (int i = 0; i < 8; i++) {
                int j = tid + 256 * i;   // 0..2047
                int row = j >> 5, cq = j & 31;
                int grow = m0 + (row >> 4) * 32 + mt * 16 + (row & 15);
                int bb = (grow >= 5120) + (grow >= 10240) + (grow >= 15360);
                float* orow = out + (size_t)(grow + 1024 * (bb + 1)) * 256 + n0 + cq * 4;
                float4 cur = *(float4*)orow;
                const float* sp = &ep[row * 132 + cq * 4];
                cur.x += sp[0]; cur.y += sp[1]; cur.z += sp[2]; cur.w += sp[3];
                *(float4*)orow = cur;
            }
        }
    }
}

// ---------------- launch ----------------
extern "C" void kernel_launch(void* const* d_in, const int* in_sizes, int n_in,
                              void* d_out, int out_size) {
    const float* x    = (const float*)d_in[0];
    const float* ref  = (const float*)d_in[1];
    const float* n1g = (const float*)d_in[7];
    const float* n1b = (const float*)d_in[8];
    const float* awW = (const float*)d_in[9];
    const float* awb = (const float*)d_in[10];
    const float* soW = (const float*)d_in[11];
    const float* sob = (const float*)d_in[12];
    const float* n2g  = (const float*)d_in[23];
    const float* n2b  = (const float*)d_in[24];
    const float* fc1W = (const float*)d_in[25];
    const float* fc1b = (const float*)d_in[26];
    const float* fc2W = (const float*)d_in[27];
    const float* fc2b = (const float*)d_in[28];
    float* out = (float*)d_out;

    ProjParams P;
    for (int lvl = 0; lvl < 5; lvl++) {
        P.feat[lvl] = (const float*)d_in[2 + lvl];
        P.W[lvl]    = (const float*)d_in[13 + 2 * lvl];
        P.bias[lvl] = (const float*)d_in[14 + 2 * lvl];
    }

    convert_w<<<1920, 256>>>(fc1W, fc2W, P.bias[2], P.bias[3], P.bias[4], x, out);
    proj_all<<<1504, 256>>>(P);
    token_fused<<<1280, 256>>>(x, ref, n1g, n1b, awW, awb, soW, sob, n2g, n2b, out);
    mma_gemm<256, 512, 0><<<dim3(4, 160), 256>>>(fc1b, out);
    mma_gemm<512, 256, 1><<<dim3(2, 160), 256>>>(fc2b, out);
}